// round 8
// baseline (speedup 1.0000x reference)
#include <cuda_runtime.h>
#include <math.h>
#include <stdint.h>
#include <stddef.h>

#define BDIM 16384
#define CB   8
#define KK   256
#define DD   512
#define NCOL (CB*KK)              /* 2048 */
#define NIDX (BDIM*CB)            /* 131072 */
#define NTOT ((size_t)BDIM*NCOL)  /* 33554432 per iteration */
#define NXB  1024

// ---------------- static device scratch (no allocations allowed) ----------------
static __device__ float d_X0[(size_t)BDIM*NCOL];    // x @ centers^T       (134MB)
static __device__ float d_G2[(size_t)NCOL*NCOL];    // centers @ centers^T (16MB)
static __device__ float d_Pb[(size_t)BDIM*NCOL];    // per-frame probs, last iter
static __device__ float d_gum4[(size_t)4*BDIM*NCOL];// gumbel noise, 4 iters (536MB)
static __device__ float d_censq[NCOL];
static __device__ float d_asq[NIDX];
static __device__ int   d_idx[2][NIDX];
static __device__ float d_Hb[NIDX];
static __device__ float d_ESb[NIDX];
static __device__ float d_Pc[32][NCOL];
static __device__ float d_xsqp[NXB];

// ---------------- Threefry-2x32-20 (exact JAX semantics) ----------------
__host__ __device__ __forceinline__ unsigned rotl32(unsigned x, int r) {
    return (x << r) | (x >> (32 - r));
}
__host__ __device__ __forceinline__ void tf2x32(unsigned k0, unsigned k1,
                                                unsigned& x0, unsigned& x1) {
    unsigned k2 = k0 ^ k1 ^ 0x1BD11BDAu;
    x0 += k0; x1 += k1;
#define TFR(r) { x0 += x1; x1 = rotl32(x1, (r)); x1 ^= x0; }
    TFR(13) TFR(15) TFR(26) TFR(6)   x0 += k1; x1 += k2 + 1u;
    TFR(17) TFR(29) TFR(16) TFR(24)  x0 += k2; x1 += k0 + 2u;
    TFR(13) TFR(15) TFR(26) TFR(6)   x0 += k0; x1 += k1 + 3u;
    TFR(17) TFR(29) TFR(16) TFR(24)  x0 += k1; x1 += k2 + 4u;
    TFR(13) TFR(15) TFR(26) TFR(6)   x0 += k2; x1 += k0 + 5u;
#undef TFR
}

__device__ __forceinline__ float gumbel_from_bits(unsigned r) {
    float f = __uint_as_float((r >> 9) | 0x3f800000u) - 1.0f;
    float u = (f == 0.0f) ? 1.17549435e-38f : f;
    return -logf(-logf(u));
}

// jax_threefry_partitionable random_bits: elem e -> threefry(key,(0,e)), o0^o1
__device__ __forceinline__ float gumbel_elem(unsigned k0, unsigned k1, unsigned e) {
    unsigned x0 = 0u, x1 = e;
    tf2x32(k0, k1, x0, x1);
    return gumbel_from_bits(x0 ^ x1);
}

// ---------------- cp.async helpers ----------------
__device__ __forceinline__ uint32_t smem_u32(const void* p) {
    uint32_t a;
    asm("{ .reg .u64 t; cvta.to.shared.u64 t, %1; cvt.u32.u64 %0, t; }" : "=r"(a) : "l"(p));
    return a;
}
#define CP_ASYNC16(d, s) asm volatile("cp.async.cg.shared.global [%0], [%1], 16;" :: "r"(d), "l"(s) : "memory")
#define CP_COMMIT()      asm volatile("cp.async.commit_group;" ::: "memory")
#define CP_WAIT0()       asm volatile("cp.async.wait_group 0;" ::: "memory")

// ---------------- small kernels ----------------
__global__ void init_k(const int* __restrict__ init_idx) {
    int t = blockIdx.x * blockDim.x + threadIdx.x;
    if (t < NIDX) d_idx[0][t] = init_idx[t];
}

__global__ void censq_k(const float* __restrict__ centers) {
    int row = blockIdx.x;                  // 0..2047
    const float* cc = centers + (size_t)row * DD;
    float p = 0.0f;
    for (int d = threadIdx.x; d < DD; d += 128) p = fmaf(cc[d], cc[d], p);
    #pragma unroll
    for (int off = 16; off; off >>= 1) p += __shfl_xor_sync(0xffffffffu, p, off);
    __shared__ float red[4];
    if ((threadIdx.x & 31) == 0) red[threadIdx.x >> 5] = p;
    __syncthreads();
    if (threadIdx.x == 0) d_censq[row] = ((red[0] + red[1]) + (red[2] + red[3]));
}

__global__ void xsq_k(const float* __restrict__ x) {
    const size_t N = (size_t)BDIM * DD;
    float p = 0.0f;
    for (size_t i = (size_t)blockIdx.x * blockDim.x + threadIdx.x; i < N;
         i += (size_t)gridDim.x * blockDim.x)
        p = fmaf(x[i], x[i], p);
    #pragma unroll
    for (int off = 16; off; off >>= 1) p += __shfl_xor_sync(0xffffffffu, p, off);
    __shared__ float red[8];
    if ((threadIdx.x & 31) == 0) red[threadIdx.x >> 5] = p;
    __syncthreads();
    if (threadIdx.x == 0) {
        float s = 0.0f;
        #pragma unroll
        for (int w = 0; w < 8; w++) s += red[w];
        d_xsqp[blockIdx.x] = s;
    }
}

// ---------------- gumbel generator (dedicated, 16-reg, full occupancy) ----------------
__global__ void gumbel4_k(unsigned k0, unsigned k1, int iter) {
    unsigned t = blockIdx.x * blockDim.x + threadIdx.x;   // element index (< 2^25)
    float* dst = d_gum4 + (size_t)iter * NTOT;
    dst[t] = gumbel_elem(k0, k1, t);
}

// ---------------- SGEMM with register-prefetch pipeline (round-7, proven) ----------------
__global__ __launch_bounds__(256, 2)
void gemm_k(const float* __restrict__ A, const float* __restrict__ centers,
            float* __restrict__ out) {
    __shared__ float As[16][68];
    __shared__ float Bs[16][256];
    const int tid = threadIdx.x;
    const int w = tid >> 5, l = tid & 31;
    const int cy = blockIdx.y;
    const int r0 = blockIdx.x * 64;

    const int lr = tid >> 2, lq = tid & 3;
    const float* aP = A + (size_t)(r0 + lr) * DD + lq * 4;
    const int bk = tid >> 1, bd = (tid & 1) * 8;
    const float* b0P = centers + ((size_t)cy * KK + bk) * DD + bd;
    const float* b1P = centers + ((size_t)cy * KK + 128 + bk) * DD + bd;

    float acc[8][8];
    #pragma unroll
    for (int i = 0; i < 8; i++)
        #pragma unroll
        for (int j = 0; j < 8; j++) acc[i][j] = 0.0f;

    float4 a4 = *(const float4*)(aP);
    float4 q0 = *(const float4*)(b0P);
    float4 q1 = *(const float4*)(b0P + 4);
    float4 q2 = *(const float4*)(b1P);
    float4 q3 = *(const float4*)(b1P + 4);

    for (int kb = 0; kb < 32; kb++) {
        __syncthreads();
        As[lq*4+0][lr] = a4.x; As[lq*4+1][lr] = a4.y;
        As[lq*4+2][lr] = a4.z; As[lq*4+3][lr] = a4.w;
        Bs[bd+0][bk] = q0.x; Bs[bd+1][bk] = q0.y;
        Bs[bd+2][bk] = q0.z; Bs[bd+3][bk] = q0.w;
        Bs[bd+4][bk] = q1.x; Bs[bd+5][bk] = q1.y;
        Bs[bd+6][bk] = q1.z; Bs[bd+7][bk] = q1.w;
        Bs[bd+0][128+bk] = q2.x; Bs[bd+1][128+bk] = q2.y;
        Bs[bd+2][128+bk] = q2.z; Bs[bd+3][128+bk] = q2.w;
        Bs[bd+4][128+bk] = q3.x; Bs[bd+5][128+bk] = q3.y;
        Bs[bd+6][128+bk] = q3.z; Bs[bd+7][128+bk] = q3.w;
        __syncthreads();
        if (kb < 31) {
            const int d0 = (kb + 1) * 16;
            a4 = *(const float4*)(aP + d0);
            q0 = *(const float4*)(b0P + d0);
            q1 = *(const float4*)(b0P + d0 + 4);
            q2 = *(const float4*)(b1P + d0);
            q3 = *(const float4*)(b1P + d0 + 4);
        }
        #pragma unroll
        for (int d = 0; d < 16; d++) {
            float4 a0 = *(const float4*)&As[d][w*8];
            float4 a1 = *(const float4*)&As[d][w*8+4];
            float4 bb0 = *(const float4*)&Bs[d][l*8];
            float4 bb1 = *(const float4*)&Bs[d][l*8+4];
            float av[8] = {a0.x,a0.y,a0.z,a0.w,a1.x,a1.y,a1.z,a1.w};
            float bv[8] = {bb0.x,bb0.y,bb0.z,bb0.w,bb1.x,bb1.y,bb1.z,bb1.w};
            #pragma unroll
            for (int i = 0; i < 8; i++)
                #pragma unroll
                for (int j = 0; j < 8; j++)
                    acc[i][j] = fmaf(av[i], bv[j], acc[i][j]);
        }
    }

    #pragma unroll
    for (int i = 0; i < 8; i++) {
        float* o = out + (size_t)(r0 + w*8 + i) * NCOL + cy * KK + l * 8;
        float4 v0 = make_float4(acc[i][0], acc[i][1], acc[i][2], acc[i][3]);
        float4 v1 = make_float4(acc[i][4], acc[i][5], acc[i][6], acc[i][7]);
        *(float4*)o = v0;
        *(float4*)(o + 4) = v1;
    }
}

// ---------------- per-iteration a_sq ----------------
__global__ __launch_bounds__(256)
void asq_k(const float* __restrict__ x, const float* __restrict__ centers, int cur) {
    __shared__ float cens[CB][DD];
    __shared__ float xe[DD];
    __shared__ int ids[CB];
    const int b = blockIdx.x, tid = threadIdx.x;
    const int w = tid >> 5, l = tid & 31;
    if (tid < CB) ids[tid] = d_idx[cur][b * CB + tid];
    __syncthreads();
    for (int t = tid; t < CB * DD; t += 256) {
        int c = t >> 9, d = t & 511;
        cens[c][d] = centers[((size_t)c * KK + ids[c]) * DD + d];
    }
    __syncthreads();
    #pragma unroll
    for (int q = 0; q < 2; q++) {
        int d = tid + q * 256;
        float s = 0.0f;
        #pragma unroll
        for (int c = 0; c < CB; c++) s += cens[c][d];
        xe[d] = s - x[(size_t)b * DD + d];
    }
    __syncthreads();
    float p = 0.0f;
    #pragma unroll
    for (int it = 0; it < 16; it++) {
        int d = l + it * 32;
        float a = xe[d] - cens[w][d];
        p = fmaf(a, a, p);
    }
    #pragma unroll
    for (int off = 16; off; off >>= 1) p += __shfl_xor_sync(0xffffffffu, p, off);
    if (l == 0) d_asq[b * CB + w] = p;
}

// ---------------- fused refine (round-6 body: loads gumbel row; proven identical) ----------------
// dynamic smem: G2 rows[8][2048] | X0 row[2048] | censq[2048] | S[2048] | gum[2048]
#define RSM_FLOATS (12*NCOL)
__global__ void __launch_bounds__(256)
ref_k(const float* __restrict__ fes, int cur, int nxt, int last, int iter) {
    extern __shared__ float sm[];
    float* G2s = sm;                 // 8 rows
    float* X0s = sm + 8 * NCOL;
    float* CSs = sm + 9 * NCOL;
    float* Ss  = sm + 10 * NCOL;
    float* Gms = sm + 11 * NCOL;
    __shared__ int ids[CB];

    const int tid = threadIdx.x;
    const int w = tid >> 5, l = tid & 31;
    const int b = blockIdx.x;

    if (tid < CB) ids[tid] = d_idx[cur][b * CB + tid];
    __syncthreads();

    {
        #pragma unroll
        for (int c = 0; c < CB; c++) {
            const float4* src = (const float4*)(d_G2 + (size_t)(c * KK + ids[c]) * NCOL);
            uint32_t dst = smem_u32(G2s + c * NCOL);
            CP_ASYNC16(dst + tid * 16, src + tid);
            CP_ASYNC16(dst + (tid + 256) * 16, src + tid + 256);
        }
        const float4* sx = (const float4*)(d_X0 + (size_t)b * NCOL);
        uint32_t dx = smem_u32(X0s);
        CP_ASYNC16(dx + tid * 16, sx + tid);
        CP_ASYNC16(dx + (tid + 256) * 16, sx + tid + 256);
        const float4* sc = (const float4*)(d_censq);
        uint32_t dc = smem_u32(CSs);
        CP_ASYNC16(dc + tid * 16, sc + tid);
        CP_ASYNC16(dc + (tid + 256) * 16, sc + tid + 256);
        const float4* sg = (const float4*)(d_gum4 + (size_t)iter * NTOT + (size_t)b * NCOL);
        uint32_t dg = smem_u32(Gms);
        CP_ASYNC16(dg + tid * 16, sg + tid);
        CP_ASYNC16(dg + (tid + 256) * 16, sg + tid + 256);
        CP_COMMIT();
        CP_WAIT0();
    }
    __syncthreads();

    #pragma unroll
    for (int q = 0; q < 8; q++) {
        int col = tid + q * 256;
        float s = 0.0f;
        #pragma unroll
        for (int c = 0; c < CB; c++) s += G2s[c * NCOL + col];
        Ss[col] = s;
    }
    __syncthreads();

    const int c = w;
    const float asq = d_asq[b * CB + c];
    const float scale = expf(fes[0]);

    float vs[8];
    float bestS = -INFINITY; int bestK = 0;
    #pragma unroll
    for (int j = 0; j < 8; j++) {
        int k = l + 32 * j;
        int col = c * KK + k;
        float cross = (Ss[col] - X0s[col]) - G2s[c * NCOL + col];
        float v = -((asq + 2.0f * cross) + CSs[col]);   // reference grouping
        vs[j] = v;
        float g = Gms[col];
        float s = scale * v + g;
        if (s > bestS || (s == bestS && k < bestK)) { bestS = s; bestK = k; }
    }
    #pragma unroll
    for (int off = 16; off; off >>= 1) {
        float oS = __shfl_xor_sync(0xffffffffu, bestS, off);
        int   oK = __shfl_xor_sync(0xffffffffu, bestK, off);
        if (oS > bestS || (oS == bestS && oK < bestK)) { bestS = oS; bestK = oK; }
    }
    if (l == 0) d_idx[nxt][b * CB + c] = bestK;

    if (last) {
        float m = -INFINITY;
        #pragma unroll
        for (int j = 0; j < 8; j++) m = fmaxf(m, scale * vs[j]);
        #pragma unroll
        for (int off = 16; off; off >>= 1)
            m = fmaxf(m, __shfl_xor_sync(0xffffffffu, m, off));
        float se = 0.0f;
        #pragma unroll
        for (int j = 0; j < 8; j++) se += expf(scale * vs[j] - m);
        #pragma unroll
        for (int off = 16; off; off >>= 1)
            se += __shfl_xor_sync(0xffffffffu, se, off);
        float lse = m + logf(se);
        float H = 0.0f, ES = 0.0f;
        #pragma unroll
        for (int j = 0; j < 8; j++) {
            int k = l + 32 * j;
            float lp = scale * vs[j] - lse;
            float p = expf(lp);
            H  = fmaf(-p, lp, H);
            ES = fmaf(p, -vs[j], ES);
            d_Pb[(size_t)b * NCOL + c * KK + k] = p;
        }
        #pragma unroll
        for (int off = 16; off; off >>= 1) {
            H  += __shfl_xor_sync(0xffffffffu, H, off);
            ES += __shfl_xor_sync(0xffffffffu, ES, off);
        }
        if (l == 0) { d_Hb[b * CB + c] = H; d_ESb[b * CB + c] = ES; }
    }
}

// ---------------- last-iter column sums of probs (deterministic) ----------------
__global__ void colsum_k() {
    const int col = blockIdx.y * 256 + threadIdx.x;
    const int bx = blockIdx.x;             // 32 b-chunks of 512
    float s = 0.0f;
    for (int b = bx * 512; b < (bx + 1) * 512; b++)
        s += d_Pb[(size_t)b * NCOL + col];
    d_Pc[bx][col] = s;
}

// ---------------- outputs ----------------
__global__ void outidx_k(float* out, int out_size) {
    int t = blockIdx.x * blockDim.x + threadIdx.x;
    if (t < NIDX && t < out_size) out[t] = (float)d_idx[0][t];
}

__global__ void scal_k(float* out, int out_size) {
    const int t = threadIdx.x;
    __shared__ float sh[256];

    float v = 0.0f;
    for (int i = t; i < NXB; i += 256) v += d_xsqp[i];
    sh[t] = v; __syncthreads();
    for (int s = 128; s; s >>= 1) { if (t < s) sh[t] += sh[t + s]; __syncthreads(); }
    float xsq = sh[0]; __syncthreads();

    v = 0.0f;
    for (int i = t; i < NIDX; i += 256) v += d_Hb[i];
    sh[t] = v; __syncthreads();
    for (int s = 128; s; s >>= 1) { if (t < s) sh[t] += sh[t + s]; __syncthreads(); }
    float Hs = sh[0]; __syncthreads();

    v = 0.0f;
    for (int i = t; i < NIDX; i += 256) v += d_ESb[i];
    sh[t] = v; __syncthreads();
    for (int s = 128; s; s >>= 1) { if (t < s) sh[t] += sh[t + s]; __syncthreads(); }
    float ESs = sh[0]; __syncthreads();

    v = 0.0f;
    for (int col = t; col < NCOL; col += 256) {
        float s = 0.0f;
        #pragma unroll
        for (int bx = 0; bx < 32; bx++) s += d_Pc[bx][col];
        float avg = s / (float)BDIM;
        v += -avg * logf(avg + 1e-20f);
    }
    sh[t] = v; __syncthreads();
    for (int s = 128; s; s >>= 1) { if (t < s) sh[t] += sh[t + s]; __syncthreads(); }
    float cent = sh[0];

    if (t == 0 && out_size >= NIDX + 3) {
        out[NIDX + 0] = logf((float)KK) - cent / (float)CB;  // entropy_loss
        out[NIDX + 1] = Hs / (float)NIDX;                    // frame_entropy
        out[NIDX + 2] = (ESs / (float)CB) / (xsq + 1e-20f);  // reconstruction_loss
    }
}

// ---------------- launch ----------------
extern "C" void kernel_launch(void* const* d_in, const int* in_sizes, int n_in,
                              void* d_out, int out_size) {
    const float* x       = (const float*)d_in[0];
    const float* centers = (const float*)d_in[1];
    const float* fes     = (const float*)d_in[2];
    const int*   init_i  = (const int*)d_in[3];
    float* out = (float*)d_out;
    (void)in_sizes; (void)n_in;

    // one-time host-side setup (first call is the non-captured correctness run)
    static cudaStream_t s2 = 0;
    static cudaEvent_t evF = 0, evJ = 0;
    static int once = 0;
    if (!once) {
        cudaFuncSetAttribute(ref_k, cudaFuncAttributeMaxDynamicSharedMemorySize,
                             RSM_FLOATS * 4);
        cudaStreamCreateWithFlags(&s2, cudaStreamNonBlocking);
        cudaEventCreateWithFlags(&evF, cudaEventDisableTiming);
        cudaEventCreateWithFlags(&evJ, cudaEventDisableTiming);
        once = 1;
    }

    // fork: gumbel generation (input-independent, ALU-bound) on s2,
    // concurrent with the fma-bound GEMMs on the main stream.
    cudaEventRecord(evF, 0);
    cudaStreamWaitEvent(s2, evF, 0);
    for (int i = 0; i < 4; i++) {
        unsigned fk0 = 0u, fk1 = (unsigned)i;
        tf2x32(0u, 1234u, fk0, fk1);   // fold_in(key(1234), i)
        gumbel4_k<<<NTOT / 256, 256, 0, s2>>>(fk0, fk1, i);
    }
    cudaEventRecord(evJ, s2);

    init_k<<<(NIDX + 255) / 256, 256>>>(init_i);
    censq_k<<<NCOL, 128>>>(centers);
    xsq_k<<<NXB, 256>>>(x);

    // one-time GEMMs: G2 = CF @ CF^T, X0 = x @ CF^T
    {
        float* G2p; cudaGetSymbolAddress((void**)&G2p, d_G2);
        float* X0p; cudaGetSymbolAddress((void**)&X0p, d_X0);
        dim3 gg(NCOL / 64, CB);
        gemm_k<<<gg, 256>>>(centers, centers, G2p);
        dim3 gx(BDIM / 64, CB);
        gemm_k<<<gx, 256>>>(x, centers, X0p);
    }

    // join: iterations need the gumbel buffers
    cudaStreamWaitEvent(0, evJ, 0);

    for (int i = 0; i < 4; i++) {
        asq_k<<<BDIM, 256>>>(x, centers, i & 1);
        ref_k<<<BDIM, 256, RSM_FLOATS * 4>>>(fes, i & 1, (i + 1) & 1,
                                             (i == 3) ? 1 : 0, i);
    }

    {
        dim3 gc(32, CB);
        colsum_k<<<gc, 256>>>();
    }
    outidx_k<<<(NIDX + 255) / 256, 256>>>(out, out_size);
    scal_k<<<1, 256>>>(out, out_size);
}

// round 10
// speedup vs baseline: 1.1219x; 1.1219x over previous
#include <cuda_runtime.h>
#include <math.h>
#include <stdint.h>
#include <stddef.h>

#define BDIM 16384
#define CB   8
#define KK   256
#define DD   512
#define NCOL (CB*KK)              /* 2048 */
#define NIDX (BDIM*CB)            /* 131072 */
#define NXB  1024

// ---------------- static device scratch (no allocations allowed) ----------------
static __device__ float d_X0[(size_t)BDIM*NCOL];   // x @ centers^T       (134MB)
static __device__ float d_G2[(size_t)NCOL*NCOL];   // centers @ centers^T (16MB)
static __device__ float d_Pb[(size_t)BDIM*NCOL];   // per-frame probs, last iter (134MB)
static __device__ float d_censq[NCOL];
static __device__ float d_asq[NIDX];
static __device__ int   d_idx[2][NIDX];
static __device__ float d_Hb[NIDX];
static __device__ float d_ESb[NIDX];
static __device__ float d_Pc[32][NCOL];
static __device__ float d_xsqp[NXB];

// ---------------- Threefry-2x32-20 (exact JAX semantics) ----------------
__host__ __device__ __forceinline__ unsigned rotl32(unsigned x, int r) {
    return (x << r) | (x >> (32 - r));
}
__host__ __device__ __forceinline__ void tf2x32(unsigned k0, unsigned k1,
                                                unsigned& x0, unsigned& x1) {
    unsigned k2 = k0 ^ k1 ^ 0x1BD11BDAu;
    x0 += k0; x1 += k1;
#define TFR(r) { x0 += x1; x1 = rotl32(x1, (r)); x1 ^= x0; }
    TFR(13) TFR(15) TFR(26) TFR(6)   x0 += k1; x1 += k2 + 1u;
    TFR(17) TFR(29) TFR(16) TFR(24)  x0 += k2; x1 += k0 + 2u;
    TFR(13) TFR(15) TFR(26) TFR(6)   x0 += k0; x1 += k1 + 3u;
    TFR(17) TFR(29) TFR(16) TFR(24)  x0 += k1; x1 += k2 + 4u;
    TFR(13) TFR(15) TFR(26) TFR(6)   x0 += k2; x1 += k0 + 5u;
#undef TFR
}

__device__ __forceinline__ float gumbel_from_bits(unsigned r) {
    float f = __uint_as_float((r >> 9) | 0x3f800000u) - 1.0f;
    float u = (f == 0.0f) ? 1.17549435e-38f : f;
    return -logf(-logf(u));
}

// jax_threefry_partitionable random_bits: elem e -> threefry(key,(0,e)), o0^o1
__device__ __forceinline__ float gumbel_elem(unsigned k0, unsigned k1, unsigned e) {
    unsigned x0 = 0u, x1 = e;
    tf2x32(k0, k1, x0, x1);
    return gumbel_from_bits(x0 ^ x1);
}

// ---------------- packed f32x2 helpers (Blackwell FFMA2) ----------------
__device__ __forceinline__ unsigned long long packdup_f32(float a) {
    unsigned long long p;
    asm("mov.b64 %0, {%1, %1};" : "=l"(p) : "f"(a));
    return p;
}
__device__ __forceinline__ void fma2(unsigned long long& d, unsigned long long a,
                                     unsigned long long b) {
    asm("fma.rn.f32x2 %0, %1, %2, %0;" : "+l"(d) : "l"(a), "l"(b));
}
__device__ __forceinline__ void unpack_f32x2(float& lo, float& hi,
                                             unsigned long long p) {
    asm("mov.b64 {%0, %1}, %2;" : "=f"(lo), "=f"(hi) : "l"(p));
}

// ---------------- cp.async helpers ----------------
__device__ __forceinline__ uint32_t smem_u32(const void* p) {
    uint32_t a;
    asm("{ .reg .u64 t; cvta.to.shared.u64 t, %1; cvt.u32.u64 %0, t; }" : "=r"(a) : "l"(p));
    return a;
}
#define CP_ASYNC16(d, s) asm volatile("cp.async.cg.shared.global [%0], [%1], 16;" :: "r"(d), "l"(s) : "memory")
#define CP_COMMIT()      asm volatile("cp.async.commit_group;" ::: "memory")
#define CP_WAIT0()       asm volatile("cp.async.wait_group 0;" ::: "memory")

// ---------------- small kernels ----------------
__global__ void init_k(const int* __restrict__ init_idx) {
    int t = blockIdx.x * blockDim.x + threadIdx.x;
    if (t < NIDX) d_idx[0][t] = init_idx[t];
}

__global__ void censq_k(const float* __restrict__ centers) {
    int row = blockIdx.x;                  // 0..2047
    const float* cc = centers + (size_t)row * DD;
    float p = 0.0f;
    for (int d = threadIdx.x; d < DD; d += 128) p = fmaf(cc[d], cc[d], p);
    #pragma unroll
    for (int off = 16; off; off >>= 1) p += __shfl_xor_sync(0xffffffffu, p, off);
    __shared__ float red[4];
    if ((threadIdx.x & 31) == 0) red[threadIdx.x >> 5] = p;
    __syncthreads();
    if (threadIdx.x == 0) d_censq[row] = ((red[0] + red[1]) + (red[2] + red[3]));
}

__global__ void xsq_k(const float* __restrict__ x) {
    const size_t N = (size_t)BDIM * DD;
    float p = 0.0f;
    for (size_t i = (size_t)blockIdx.x * blockDim.x + threadIdx.x; i < N;
         i += (size_t)gridDim.x * blockDim.x)
        p = fmaf(x[i], x[i], p);
    #pragma unroll
    for (int off = 16; off; off >>= 1) p += __shfl_xor_sync(0xffffffffu, p, off);
    __shared__ float red[8];
    if ((threadIdx.x & 31) == 0) red[threadIdx.x >> 5] = p;
    __syncthreads();
    if (threadIdx.x == 0) {
        float s = 0.0f;
        #pragma unroll
        for (int w = 0; w < 8; w++) s += red[w];
        d_xsqp[blockIdx.x] = s;
    }
}

// ---------------- SGEMM: register-prefetch pipeline + FFMA2 microkernel ----------------
// out[r][cy*256+k] = dot(A[r], centers_flat[cy*256+k]); tile 64 x 256, K(d)=512.
// Each acc[i][j] chain accumulates in identical d-order to previous rounds;
// fma.rn.f32x2 lanes are exact rn FMAs -> output bit-identical to round 7.
__global__ __launch_bounds__(256, 2)
void gemm_k(const float* __restrict__ A, const float* __restrict__ centers,
            float* __restrict__ out) {
    __shared__ float As[16][68];
    __shared__ float Bs[16][256];
    const int tid = threadIdx.x;
    const int w = tid >> 5, l = tid & 31;
    const int cy = blockIdx.y;
    const int r0 = blockIdx.x * 64;

    const int lr = tid >> 2, lq = tid & 3;
    const float* aP = A + (size_t)(r0 + lr) * DD + lq * 4;
    const int bk = tid >> 1, bd = (tid & 1) * 8;
    const float* b0P = centers + ((size_t)cy * KK + bk) * DD + bd;
    const float* b1P = centers + ((size_t)cy * KK + 128 + bk) * DD + bd;

    // packed accumulators: accp[i][jp] = (acc[i][2jp], acc[i][2jp+1])
    unsigned long long accp[8][4];
    #pragma unroll
    for (int i = 0; i < 8; i++)
        #pragma unroll
        for (int j = 0; j < 4; j++) accp[i][j] = 0ull;

    // prologue: load chunk 0
    float4 a4 = *(const float4*)(aP);
    float4 q0 = *(const float4*)(b0P);
    float4 q1 = *(const float4*)(b0P + 4);
    float4 q2 = *(const float4*)(b1P);
    float4 q3 = *(const float4*)(b1P + 4);

    for (int kb = 0; kb < 32; kb++) {
        __syncthreads();     // previous chunk's compute done; smem free
        As[lq*4+0][lr] = a4.x; As[lq*4+1][lr] = a4.y;
        As[lq*4+2][lr] = a4.z; As[lq*4+3][lr] = a4.w;
        Bs[bd+0][bk] = q0.x; Bs[bd+1][bk] = q0.y;
        Bs[bd+2][bk] = q0.z; Bs[bd+3][bk] = q0.w;
        Bs[bd+4][bk] = q1.x; Bs[bd+5][bk] = q1.y;
        Bs[bd+6][bk] = q1.z; Bs[bd+7][bk] = q1.w;
        Bs[bd+0][128+bk] = q2.x; Bs[bd+1][128+bk] = q2.y;
        Bs[bd+2][128+bk] = q2.z; Bs[bd+3][128+bk] = q2.w;
        Bs[bd+4][128+bk] = q3.x; Bs[bd+5][128+bk] = q3.y;
        Bs[bd+6][128+bk] = q3.z; Bs[bd+7][128+bk] = q3.w;
        __syncthreads();
        if (kb < 31) {       // prefetch chunk kb+1; latency hidden by compute below
            const int d0 = (kb + 1) * 16;
            a4 = *(const float4*)(aP + d0);
            q0 = *(const float4*)(b0P + d0);
            q1 = *(const float4*)(b0P + d0 + 4);
            q2 = *(const float4*)(b1P + d0);
            q3 = *(const float4*)(b1P + d0 + 4);
        }
        #pragma unroll
        for (int d = 0; d < 16; d++) {
            float4 a0 = *(const float4*)&As[d][w*8];
            float4 a1 = *(const float4*)&As[d][w*8+4];
            // B pairs read directly as 64-bit packed (adjacent k columns)
            ulonglong2 bp0 = *(const ulonglong2*)&Bs[d][l*8];
            ulonglong2 bp1 = *(const ulonglong2*)&Bs[d][l*8+4];
            unsigned long long bp[4] = {bp0.x, bp0.y, bp1.x, bp1.y};
            float av[8] = {a0.x,a0.y,a0.z,a0.w,a1.x,a1.y,a1.z,a1.w};
            #pragma unroll
            for (int i = 0; i < 8; i++) {
                unsigned long long ad = packdup_f32(av[i]);
                #pragma unroll
                for (int j = 0; j < 4; j++)
                    fma2(accp[i][j], ad, bp[j]);
            }
        }
    }

    #pragma unroll
    for (int i = 0; i < 8; i++) {
        float* o = out + (size_t)(r0 + w*8 + i) * NCOL + cy * KK + l * 8;
        float4 v0, v1;
        unpack_f32x2(v0.x, v0.y, accp[i][0]);
        unpack_f32x2(v0.z, v0.w, accp[i][1]);
        unpack_f32x2(v1.x, v1.y, accp[i][2]);
        unpack_f32x2(v1.z, v1.w, accp[i][3]);
        *(float4*)o = v0;
        *(float4*)(o + 4) = v1;
    }
}

// ---------------- per-iteration a_sq ----------------
__global__ __launch_bounds__(256)
void asq_k(const float* __restrict__ x, const float* __restrict__ centers, int cur) {
    __shared__ float cens[CB][DD];
    __shared__ float xe[DD];
    __shared__ int ids[CB];
    const int b = blockIdx.x, tid = threadIdx.x;
    const int w = tid >> 5, l = tid & 31;
    if (tid < CB) ids[tid] = d_idx[cur][b * CB + tid];
    __syncthreads();
    for (int t = tid; t < CB * DD; t += 256) {
        int c = t >> 9, d = t & 511;
        cens[c][d] = centers[((size_t)c * KK + ids[c]) * DD + d];
    }
    __syncthreads();
    #pragma unroll
    for (int q = 0; q < 2; q++) {
        int d = tid + q * 256;
        float s = 0.0f;
        #pragma unroll
        for (int c = 0; c < CB; c++) s += cens[c][d];
        xe[d] = s - x[(size_t)b * DD + d];
    }
    __syncthreads();
    // warp-per-codebook
    float p = 0.0f;
    #pragma unroll
    for (int it = 0; it < 16; it++) {
        int d = l + it * 32;
        float a = xe[d] - cens[w][d];
        p = fmaf(a, a, p);
    }
    #pragma unroll
    for (int off = 16; off; off >>= 1) p += __shfl_xor_sync(0xffffffffu, p, off);
    if (l == 0) d_asq[b * CB + w] = p;
}

// ---------------- fused refine: gather + combine + gumbel-argmax + stats ----------------
// dynamic smem: G2 rows[8][2048] | X0 row[2048] | censq[2048] | S[2048]
#define RSM_FLOATS (8*NCOL + 3*NCOL)
__global__ void __launch_bounds__(256)
ref_k(const float* __restrict__ fes, int cur, int nxt, int last,
      unsigned fk0, unsigned fk1) {
    extern __shared__ float sm[];
    float* G2s = sm;                 // 8 rows
    float* X0s = sm + 8 * NCOL;
    float* CSs = sm + 9 * NCOL;
    float* Ss  = sm + 10 * NCOL;
    __shared__ int ids[CB];

    const int tid = threadIdx.x;
    const int w = tid >> 5, l = tid & 31;
    const int b = blockIdx.x;

    if (tid < CB) ids[tid] = d_idx[cur][b * CB + tid];
    __syncthreads();

    // async load: 8 gathered G2 rows + X0 row + censq (2 float4 per row per thread)
    {
        #pragma unroll
        for (int c = 0; c < CB; c++) {
            const float4* src = (const float4*)(d_G2 + (size_t)(c * KK + ids[c]) * NCOL);
            uint32_t dst = smem_u32(G2s + c * NCOL);
            CP_ASYNC16(dst + tid * 16, src + tid);
            CP_ASYNC16(dst + (tid + 256) * 16, src + tid + 256);
        }
        const float4* sx = (const float4*)(d_X0 + (size_t)b * NCOL);
        uint32_t dx = smem_u32(X0s);
        CP_ASYNC16(dx + tid * 16, sx + tid);
        CP_ASYNC16(dx + (tid + 256) * 16, sx + tid + 256);
        const float4* sc = (const float4*)(d_censq);
        uint32_t dc = smem_u32(CSs);
        CP_ASYNC16(dc + tid * 16, sc + tid);
        CP_ASYNC16(dc + (tid + 256) * 16, sc + tid + 256);
        CP_COMMIT();
        CP_WAIT0();
    }
    __syncthreads();

    // S[col] = sum_{c'} G2row[c'][col], fixed order
    #pragma unroll
    for (int q = 0; q < 8; q++) {
        int col = tid + q * 256;
        float s = 0.0f;
        #pragma unroll
        for (int c = 0; c < CB; c++) s += G2s[c * NCOL + col];
        Ss[col] = s;
    }
    __syncthreads();

    // warp w handles codebook c = w; thread l handles k = l + 32*j
    const int c = w;
    const float asq = d_asq[b * CB + c];
    const float scale = expf(fes[0]);
    const unsigned ebase = ((unsigned)(b * CB + c)) << 8;

    float vs[8];
    float bestS = -INFINITY; int bestK = 0;
    #pragma unroll
    for (int j = 0; j < 8; j++) {
        int k = l + 32 * j;
        int col = c * KK + k;
        float cross = (Ss[col] - X0s[col]) - G2s[c * NCOL + col];
        float v = -((asq + 2.0f * cross) + CSs[col]);   // reference grouping
        vs[j] = v;
        float g = gumbel_elem(fk0, fk1, ebase + (unsigned)k);
        float s = scale * v + g;
        if (s > bestS || (s == bestS && k < bestK)) { bestS = s; bestK = k; }
    }
    #pragma unroll
    for (int off = 16; off; off >>= 1) {
        float oS = __shfl_xor_sync(0xffffffffu, bestS, off);
        int   oK = __shfl_xor_sync(0xffffffffu, bestK, off);
        if (oS > bestS || (oS == bestS && oK < bestK)) { bestS = oS; bestK = oK; }
    }
    if (l == 0) d_idx[nxt][b * CB + c] = bestK;

    if (last) {
        float m = -INFINITY;
        #pragma unroll
        for (int j = 0; j < 8; j++) m = fmaxf(m, scale * vs[j]);
        #pragma unroll
        for (int off = 16; off; off >>= 1)
            m = fmaxf(m, __shfl_xor_sync(0xffffffffu, m, off));
        float se = 0.0f;
        #pragma unroll
        for (int j = 0; j < 8; j++) se += expf(scale * vs[j] - m);
        #pragma unroll
        for (int off = 16; off; off >>= 1)
            se += __shfl_xor_sync(0xffffffffu, se, off);
        float lse = m + logf(se);
        float H = 0.0f, ES = 0.0f;
        #pragma unroll
        for (int j = 0; j < 8; j++) {
            int k = l + 32 * j;
            float lp = scale * vs[j] - lse;
            float p = expf(lp);
            H  = fmaf(-p, lp, H);
            ES = fmaf(p, -vs[j], ES);
            d_Pb[(size_t)b * NCOL + c * KK + k] = p;
        }
        #pragma unroll
        for (int off = 16; off; off >>= 1) {
            H  += __shfl_xor_sync(0xffffffffu, H, off);
            ES += __shfl_xor_sync(0xffffffffu, ES, off);
        }
        if (l == 0) { d_Hb[b * CB + c] = H; d_ESb[b * CB + c] = ES; }
    }
}

// ---------------- last-iter column sums of probs (deterministic) ----------------
__global__ void colsum_k() {
    const int col = blockIdx.y * 256 + threadIdx.x;
    const int bx = blockIdx.x;             // 32 b-chunks of 512
    float s = 0.0f;
    for (int b = bx * 512; b < (bx + 1) * 512; b++)
        s += d_Pb[(size_t)b * NCOL + col];
    d_Pc[bx][col] = s;
}

// ---------------- outputs ----------------
__global__ void outidx_k(float* out, int out_size) {
    int t = blockIdx.x * blockDim.x + threadIdx.x;
    if (t < NIDX && t < out_size) out[t] = (float)d_idx[0][t];
}

__global__ void scal_k(float* out, int out_size) {
    const int t = threadIdx.x;
    __shared__ float sh[256];

    float v = 0.0f;
    for (int i = t; i < NXB; i += 256) v += d_xsqp[i];
    sh[t] = v; __syncthreads();
    for (int s = 128; s; s >>= 1) { if (t < s) sh[t] += sh[t + s]; __syncthreads(); }
    float xsq = sh[0]; __syncthreads();

    v = 0.0f;
    for (int i = t; i < NIDX; i += 256) v += d_Hb[i];
    sh[t] = v; __syncthreads();
    for (int s = 128; s; s >>= 1) { if (t < s) sh[t] += sh[t + s]; __syncthreads(); }
    float Hs = sh[0]; __syncthreads();

    v = 0.0f;
    for (int i = t; i < NIDX; i += 256) v += d_ESb[i];
    sh[t] = v; __syncthreads();
    for (int s = 128; s; s >>= 1) { if (t < s) sh[t] += sh[t + s]; __syncthreads(); }
    float ESs = sh[0]; __syncthreads();

    v = 0.0f;
    for (int col = t; col < NCOL; col += 256) {
        float s = 0.0f;
        #pragma unroll
        for (int bx = 0; bx < 32; bx++) s += d_Pc[bx][col];
        float avg = s / (float)BDIM;
        v += -avg * logf(avg + 1e-20f);
    }
    sh[t] = v; __syncthreads();
    for (int s = 128; s; s >>= 1) { if (t < s) sh[t] += sh[t + s]; __syncthreads(); }
    float cent = sh[0];

    if (t == 0 && out_size >= NIDX + 3) {
        out[NIDX + 0] = logf((float)KK) - cent / (float)CB;  // entropy_loss
        out[NIDX + 1] = Hs / (float)NIDX;                    // frame_entropy
        out[NIDX + 2] = (ESs / (float)CB) / (xsq + 1e-20f);  // reconstruction_loss
    }
}

// ---------------- launch ----------------
extern "C" void kernel_launch(void* const* d_in, const int* in_sizes, int n_in,
                              void* d_out, int out_size) {
    const float* x       = (const float*)d_in[0];
    const float* centers = (const float*)d_in[1];
    const float* fes     = (const float*)d_in[2];
    const int*   init_i  = (const int*)d_in[3];
    float* out = (float*)d_out;
    (void)in_sizes; (void)n_in;

    static int smem_set = 0;
    if (!smem_set) {
        cudaFuncSetAttribute(ref_k, cudaFuncAttributeMaxDynamicSharedMemorySize,
                             RSM_FLOATS * 4);
        smem_set = 1;
    }

    init_k<<<(NIDX + 255) / 256, 256>>>(init_i);
    censq_k<<<NCOL, 128>>>(centers);
    xsq_k<<<NXB, 256>>>(x);

    // one-time GEMMs: G2 = CF @ CF^T, X0 = x @ CF^T
    {
        float* G2p; cudaGetSymbolAddress((void**)&G2p, d_G2);
        float* X0p; cudaGetSymbolAddress((void**)&X0p, d_X0);
        dim3 gg(NCOL / 64, CB);
        gemm_k<<<gg, 256>>>(centers, centers, G2p);
        dim3 gx(BDIM / 64, CB);
        gemm_k<<<gx, 256>>>(x, centers, X0p);
    }

    for (int i = 0; i < 4; i++) {
        unsigned fk0 = 0u, fk1 = (unsigned)i;
        tf2x32(0u, 1234u, fk0, fk1);   // fold_in(key(1234), i)
        asq_k<<<BDIM, 256>>>(x, centers, i & 1);
        ref_k<<<BDIM, 256, RSM_FLOATS * 4>>>(fes, i & 1, (i + 1) & 1,
                                             (i == 3) ? 1 : 0, fk0, fk1);
    }

    {
        dim3 gc(32, CB);
        colsum_k<<<gc, 256>>>();
    }
    outidx_k<<<(NIDX + 255) / 256, 256>>>(out, out_size);
    scal_k<<<1, 256>>>(out, out_size);
}

// round 11
// speedup vs baseline: 1.2768x; 1.1380x over previous
#include <cuda_runtime.h>
#include <math.h>
#include <stdint.h>
#include <stddef.h>

#define BDIM 16384
#define CB   8
#define KK   256
#define DD   512
#define NCOL (CB*KK)              /* 2048 */
#define NIDX (BDIM*CB)            /* 131072 */
#define NXB  1024
#define XSTR 36                   /* smem row stride for mma tiles */

// ---------------- static device scratch (no allocations allowed) ----------------
static __device__ float d_X0[(size_t)BDIM*NCOL];   // x @ centers^T       (134MB)
static __device__ float d_G2[(size_t)NCOL*NCOL];   // centers @ centers^T (16MB)
static __device__ float d_Pb[(size_t)BDIM*NCOL];   // per-frame probs, last iter (134MB)
static __device__ float d_censq[NCOL];
static __device__ float d_asq[NIDX];
static __device__ int   d_idx[2][NIDX];
static __device__ float d_Hb[NIDX];
static __device__ float d_ESb[NIDX];
static __device__ float d_Pc[32][NCOL];
static __device__ float d_xsqp[NXB];

// ---------------- Threefry-2x32-20 (exact JAX semantics) ----------------
__host__ __device__ __forceinline__ unsigned rotl32(unsigned x, int r) {
    return (x << r) | (x >> (32 - r));
}
__host__ __device__ __forceinline__ void tf2x32(unsigned k0, unsigned k1,
                                                unsigned& x0, unsigned& x1) {
    unsigned k2 = k0 ^ k1 ^ 0x1BD11BDAu;
    x0 += k0; x1 += k1;
#define TFR(r) { x0 += x1; x1 = rotl32(x1, (r)); x1 ^= x0; }
    TFR(13) TFR(15) TFR(26) TFR(6)   x0 += k1; x1 += k2 + 1u;
    TFR(17) TFR(29) TFR(16) TFR(24)  x0 += k2; x1 += k0 + 2u;
    TFR(13) TFR(15) TFR(26) TFR(6)   x0 += k0; x1 += k1 + 3u;
    TFR(17) TFR(29) TFR(16) TFR(24)  x0 += k1; x1 += k2 + 4u;
    TFR(13) TFR(15) TFR(26) TFR(6)   x0 += k2; x1 += k0 + 5u;
#undef TFR
}

__device__ __forceinline__ float gumbel_from_bits(unsigned r) {
    float f = __uint_as_float((r >> 9) | 0x3f800000u) - 1.0f;
    float u = (f == 0.0f) ? 1.17549435e-38f : f;
    return -logf(-logf(u));
}

// jax_threefry_partitionable random_bits: elem e -> threefry(key,(0,e)), o0^o1
__device__ __forceinline__ float gumbel_elem(unsigned k0, unsigned k1, unsigned e) {
    unsigned x0 = 0u, x1 = e;
    tf2x32(k0, k1, x0, x1);
    return gumbel_from_bits(x0 ^ x1);
}

// ---------------- cp.async + mma helpers ----------------
__device__ __forceinline__ uint32_t smem_u32(const void* p) {
    uint32_t a;
    asm("{ .reg .u64 t; cvta.to.shared.u64 t, %1; cvt.u32.u64 %0, t; }" : "=r"(a) : "l"(p));
    return a;
}
#define CP_ASYNC16(d, s) asm volatile("cp.async.cg.shared.global [%0], [%1], 16;" :: "r"(d), "l"(s) : "memory")
#define CP_COMMIT()      asm volatile("cp.async.commit_group;" ::: "memory")
#define CP_WAIT0()       asm volatile("cp.async.wait_group 0;" ::: "memory")

__device__ __forceinline__ uint32_t to_tf32(float v) {
    uint32_t r;
    asm("cvt.rna.tf32.f32 %0, %1;" : "=r"(r) : "f"(v));
    return r;
}
__device__ __forceinline__ void mma_tf32(float* c, const uint32_t* a,
                                         uint32_t b0, uint32_t b1) {
    asm volatile(
        "mma.sync.aligned.m16n8k8.row.col.f32.tf32.tf32.f32 "
        "{%0,%1,%2,%3}, {%4,%5,%6,%7}, {%8,%9}, {%0,%1,%2,%3};"
        : "+f"(c[0]), "+f"(c[1]), "+f"(c[2]), "+f"(c[3])
        : "r"(a[0]), "r"(a[1]), "r"(a[2]), "r"(a[3]), "r"(b0), "r"(b1));
}

// ---------------- small kernels ----------------
__global__ void init_k(const int* __restrict__ init_idx) {
    int t = blockIdx.x * blockDim.x + threadIdx.x;
    if (t < NIDX) d_idx[0][t] = init_idx[t];
}

__global__ void censq_k(const float* __restrict__ centers) {
    int row = blockIdx.x;                  // 0..2047
    const float* cc = centers + (size_t)row * DD;
    float p = 0.0f;
    for (int d = threadIdx.x; d < DD; d += 128) p = fmaf(cc[d], cc[d], p);
    #pragma unroll
    for (int off = 16; off; off >>= 1) p += __shfl_xor_sync(0xffffffffu, p, off);
    __shared__ float red[4];
    if ((threadIdx.x & 31) == 0) red[threadIdx.x >> 5] = p;
    __syncthreads();
    if (threadIdx.x == 0) d_censq[row] = ((red[0] + red[1]) + (red[2] + red[3]));
}

__global__ void xsq_k(const float* __restrict__ x) {
    const size_t N = (size_t)BDIM * DD;
    float p = 0.0f;
    for (size_t i = (size_t)blockIdx.x * blockDim.x + threadIdx.x; i < N;
         i += (size_t)gridDim.x * blockDim.x)
        p = fmaf(x[i], x[i], p);
    #pragma unroll
    for (int off = 16; off; off >>= 1) p += __shfl_xor_sync(0xffffffffu, p, off);
    __shared__ float red[8];
    if ((threadIdx.x & 31) == 0) red[threadIdx.x >> 5] = p;
    __syncthreads();
    if (threadIdx.x == 0) {
        float s = 0.0f;
        #pragma unroll
        for (int w = 0; w < 8; w++) s += red[w];
        d_xsqp[blockIdx.x] = s;
    }
}

// ---------------- scalar SGEMM (round-7, proven; used for G2 only) ----------------
__global__ __launch_bounds__(256, 2)
void gemm_k(const float* __restrict__ A, const float* __restrict__ centers,
            float* __restrict__ out) {
    __shared__ float As[16][68];
    __shared__ float Bs[16][256];
    const int tid = threadIdx.x;
    const int w = tid >> 5, l = tid & 31;
    const int cy = blockIdx.y;
    const int r0 = blockIdx.x * 64;

    const int lr = tid >> 2, lq = tid & 3;
    const float* aP = A + (size_t)(r0 + lr) * DD + lq * 4;
    const int bk = tid >> 1, bd = (tid & 1) * 8;
    const float* b0P = centers + ((size_t)cy * KK + bk) * DD + bd;
    const float* b1P = centers + ((size_t)cy * KK + 128 + bk) * DD + bd;

    float acc[8][8];
    #pragma unroll
    for (int i = 0; i < 8; i++)
        #pragma unroll
        for (int j = 0; j < 8; j++) acc[i][j] = 0.0f;

    float4 a4 = *(const float4*)(aP);
    float4 q0 = *(const float4*)(b0P);
    float4 q1 = *(const float4*)(b0P + 4);
    float4 q2 = *(const float4*)(b1P);
    float4 q3 = *(const float4*)(b1P + 4);

    for (int kb = 0; kb < 32; kb++) {
        __syncthreads();
        As[lq*4+0][lr] = a4.x; As[lq*4+1][lr] = a4.y;
        As[lq*4+2][lr] = a4.z; As[lq*4+3][lr] = a4.w;
        Bs[bd+0][bk] = q0.x; Bs[bd+1][bk] = q0.y;
        Bs[bd+2][bk] = q0.z; Bs[bd+3][bk] = q0.w;
        Bs[bd+4][bk] = q1.x; Bs[bd+5][bk] = q1.y;
        Bs[bd+6][bk] = q1.z; Bs[bd+7][bk] = q1.w;
        Bs[bd+0][128+bk] = q2.x; Bs[bd+1][128+bk] = q2.y;
        Bs[bd+2][128+bk] = q2.z; Bs[bd+3][128+bk] = q2.w;
        Bs[bd+4][128+bk] = q3.x; Bs[bd+5][128+bk] = q3.y;
        Bs[bd+6][128+bk] = q3.z; Bs[bd+7][128+bk] = q3.w;
        __syncthreads();
        if (kb < 31) {
            const int d0 = (kb + 1) * 16;
            a4 = *(const float4*)(aP + d0);
            q0 = *(const float4*)(b0P + d0);
            q1 = *(const float4*)(b0P + d0 + 4);
            q2 = *(const float4*)(b1P + d0);
            q3 = *(const float4*)(b1P + d0 + 4);
        }
        #pragma unroll
        for (int d = 0; d < 16; d++) {
            float4 a0 = *(const float4*)&As[d][w*8];
            float4 a1 = *(const float4*)&As[d][w*8+4];
            float4 bb0 = *(const float4*)&Bs[d][l*8];
            float4 bb1 = *(const float4*)&Bs[d][l*8+4];
            float av[8] = {a0.x,a0.y,a0.z,a0.w,a1.x,a1.y,a1.z,a1.w};
            float bv[8] = {bb0.x,bb0.y,bb0.z,bb0.w,bb1.x,bb1.y,bb1.z,bb1.w};
            #pragma unroll
            for (int i = 0; i < 8; i++)
                #pragma unroll
                for (int j = 0; j < 8; j++)
                    acc[i][j] = fmaf(av[i], bv[j], acc[i][j]);
        }
    }

    #pragma unroll
    for (int i = 0; i < 8; i++) {
        float* o = out + (size_t)(r0 + w*8 + i) * NCOL + cy * KK + l * 8;
        float4 v0 = make_float4(acc[i][0], acc[i][1], acc[i][2], acc[i][3]);
        float4 v1 = make_float4(acc[i][4], acc[i][5], acc[i][6], acc[i][7]);
        *(float4*)o = v0;
        *(float4*)(o + 4) = v1;
    }
}

// ---------------- X0 GEMM on tensor cores: 3xTF32 mma.sync ----------------
// out[r][n] = dot(x[r], centers_flat[n]); block tile 128x128, warp 64x32,
// K-chunks of 32 (4 k-atoms of 8). smem [row][XSTR] -> fragment reads are
// bank-conflict-free (bank = 4g+tg, a permutation of 0..31).
__global__ __launch_bounds__(256, 2)
void x0mma_k(const float* __restrict__ A, const float* __restrict__ Bm,
             float* __restrict__ out) {
    extern __shared__ uint32_t xsm[];
    uint32_t* Ah = xsm;                     // [128][XSTR]
    uint32_t* Al = xsm + 128 * XSTR;
    uint32_t* Bh = xsm + 2 * 128 * XSTR;
    uint32_t* Bl = xsm + 3 * 128 * XSTR;

    const int tid  = threadIdx.x;
    const int warp = tid >> 5, lane = tid & 31;
    const int g = lane >> 2, tg = lane & 3;
    const int mw = warp >> 2, nw = warp & 3;   // warp tile (mw*64, nw*32)
    const int r0 = blockIdx.x * 128;
    const int n0 = blockIdx.y * 128;

    float acc[4][4][4];
    #pragma unroll
    for (int i = 0; i < 4; i++)
        #pragma unroll
        for (int j = 0; j < 4; j++)
            #pragma unroll
            for (int q = 0; q < 4; q++) acc[i][j][q] = 0.0f;

    const int lrow = tid >> 3;              // 0..31 (row within 4-row group per q)
    const int lkq  = (tid & 7) * 4;         // k offset 0,4,..28

    for (int kc = 0; kc < 16; kc++) {
        const int k0g = kc * 32;
        __syncthreads();
        #pragma unroll
        for (int q = 0; q < 4; q++) {
            int m = q * 32 + lrow;
            float4 v = *(const float4*)(A + (size_t)(r0 + m) * DD + k0g + lkq);
            uint32_t h0 = to_tf32(v.x), h1 = to_tf32(v.y),
                     h2 = to_tf32(v.z), h3 = to_tf32(v.w);
            uint4 hv = make_uint4(h0, h1, h2, h3);
            uint4 lv = make_uint4(to_tf32(v.x - __uint_as_float(h0)),
                                  to_tf32(v.y - __uint_as_float(h1)),
                                  to_tf32(v.z - __uint_as_float(h2)),
                                  to_tf32(v.w - __uint_as_float(h3)));
            *(uint4*)&Ah[m * XSTR + lkq] = hv;
            *(uint4*)&Al[m * XSTR + lkq] = lv;

            float4 w4 = *(const float4*)(Bm + (size_t)(n0 + m) * DD + k0g + lkq);
            uint32_t g0 = to_tf32(w4.x), g1 = to_tf32(w4.y),
                     g2 = to_tf32(w4.z), g3 = to_tf32(w4.w);
            uint4 gv = make_uint4(g0, g1, g2, g3);
            uint4 mv = make_uint4(to_tf32(w4.x - __uint_as_float(g0)),
                                  to_tf32(w4.y - __uint_as_float(g1)),
                                  to_tf32(w4.z - __uint_as_float(g2)),
                                  to_tf32(w4.w - __uint_as_float(g3)));
            *(uint4*)&Bh[m * XSTR + lkq] = gv;
            *(uint4*)&Bl[m * XSTR + lkq] = mv;
        }
        __syncthreads();

        #pragma unroll
        for (int ka = 0; ka < 4; ka++) {
            const int kb = ka * 8;
            uint32_t bh0[4], bh1[4], bl0[4], bl1[4];
            #pragma unroll
            for (int j = 0; j < 4; j++) {
                int nn = nw * 32 + j * 8 + g;
                bh0[j] = Bh[nn * XSTR + kb + tg];
                bh1[j] = Bh[nn * XSTR + kb + tg + 4];
                bl0[j] = Bl[nn * XSTR + kb + tg];
                bl1[j] = Bl[nn * XSTR + kb + tg + 4];
            }
            #pragma unroll
            for (int i = 0; i < 4; i++) {
                int mm = mw * 64 + i * 16;
                uint32_t ah[4], al[4];
                ah[0] = Ah[(mm + g) * XSTR + kb + tg];
                ah[1] = Ah[(mm + g + 8) * XSTR + kb + tg];
                ah[2] = Ah[(mm + g) * XSTR + kb + tg + 4];
                ah[3] = Ah[(mm + g + 8) * XSTR + kb + tg + 4];
                al[0] = Al[(mm + g) * XSTR + kb + tg];
                al[1] = Al[(mm + g + 8) * XSTR + kb + tg];
                al[2] = Al[(mm + g) * XSTR + kb + tg + 4];
                al[3] = Al[(mm + g + 8) * XSTR + kb + tg + 4];
                #pragma unroll
                for (int j = 0; j < 4; j++) {
                    mma_tf32(acc[i][j], ah, bl0[j], bl1[j]);
                    mma_tf32(acc[i][j], al, bh0[j], bh1[j]);
                    mma_tf32(acc[i][j], ah, bh0[j], bh1[j]);
                }
            }
        }
    }

    #pragma unroll
    for (int i = 0; i < 4; i++) {
        int m0 = r0 + mw * 64 + i * 16;
        #pragma unroll
        for (int j = 0; j < 4; j++) {
            int n = n0 + nw * 32 + j * 8 + tg * 2;
            *(float2*)(out + (size_t)(m0 + g) * NCOL + n) =
                make_float2(acc[i][j][0], acc[i][j][1]);
            *(float2*)(out + (size_t)(m0 + g + 8) * NCOL + n) =
                make_float2(acc[i][j][2], acc[i][j][3]);
        }
    }
}

// ---------------- per-iteration a_sq ----------------
__global__ __launch_bounds__(256)
void asq_k(const float* __restrict__ x, const float* __restrict__ centers, int cur) {
    __shared__ float cens[CB][DD];
    __shared__ float xe[DD];
    __shared__ int ids[CB];
    const int b = blockIdx.x, tid = threadIdx.x;
    const int w = tid >> 5, l = tid & 31;
    if (tid < CB) ids[tid] = d_idx[cur][b * CB + tid];
    __syncthreads();
    for (int t = tid; t < CB * DD; t += 256) {
        int c = t >> 9, d = t & 511;
        cens[c][d] = centers[((size_t)c * KK + ids[c]) * DD + d];
    }
    __syncthreads();
    #pragma unroll
    for (int q = 0; q < 2; q++) {
        int d = tid + q * 256;
        float s = 0.0f;
        #pragma unroll
        for (int c = 0; c < CB; c++) s += cens[c][d];
        xe[d] = s - x[(size_t)b * DD + d];
    }
    __syncthreads();
    float p = 0.0f;
    #pragma unroll
    for (int it = 0; it < 16; it++) {
        int d = l + it * 32;
        float a = xe[d] - cens[w][d];
        p = fmaf(a, a, p);
    }
    #pragma unroll
    for (int off = 16; off; off >>= 1) p += __shfl_xor_sync(0xffffffffu, p, off);
    if (l == 0) d_asq[b * CB + w] = p;
}

// ---------------- fused refine: gather + combine + gumbel-argmax + stats ----------------
#define RSM_FLOATS (8*NCOL + 3*NCOL)
__global__ void __launch_bounds__(256)
ref_k(const float* __restrict__ fes, int cur, int nxt, int last,
      unsigned fk0, unsigned fk1) {
    extern __shared__ float sm[];
    float* G2s = sm;                 // 8 rows
    float* X0s = sm + 8 * NCOL;
    float* CSs = sm + 9 * NCOL;
    float* Ss  = sm + 10 * NCOL;
    __shared__ int ids[CB];

    const int tid = threadIdx.x;
    const int w = tid >> 5, l = tid & 31;
    const int b = blockIdx.x;

    if (tid < CB) ids[tid] = d_idx[cur][b * CB + tid];
    __syncthreads();

    {
        #pragma unroll
        for (int c = 0; c < CB; c++) {
            const float4* src = (const float4*)(d_G2 + (size_t)(c * KK + ids[c]) * NCOL);
            uint32_t dst = smem_u32(G2s + c * NCOL);
            CP_ASYNC16(dst + tid * 16, src + tid);
            CP_ASYNC16(dst + (tid + 256) * 16, src + tid + 256);
        }
        const float4* sx = (const float4*)(d_X0 + (size_t)b * NCOL);
        uint32_t dx = smem_u32(X0s);
        CP_ASYNC16(dx + tid * 16, sx + tid);
        CP_ASYNC16(dx + (tid + 256) * 16, sx + tid + 256);
        const float4* sc = (const float4*)(d_censq);
        uint32_t dc = smem_u32(CSs);
        CP_ASYNC16(dc + tid * 16, sc + tid);
        CP_ASYNC16(dc + (tid + 256) * 16, sc + tid + 256);
        CP_COMMIT();
        CP_WAIT0();
    }
    __syncthreads();

    #pragma unroll
    for (int q = 0; q < 8; q++) {
        int col = tid + q * 256;
        float s = 0.0f;
        #pragma unroll
        for (int c = 0; c < CB; c++) s += G2s[c * NCOL + col];
        Ss[col] = s;
    }
    __syncthreads();

    const int c = w;
    const float asq = d_asq[b * CB + c];
    const float scale = expf(fes[0]);
    const unsigned ebase = ((unsigned)(b * CB + c)) << 8;

    float vs[8];
    float bestS = -INFINITY; int bestK = 0;
    #pragma unroll
    for (int j = 0; j < 8; j++) {
        int k = l + 32 * j;
        int col = c * KK + k;
        float cross = (Ss[col] - X0s[col]) - G2s[c * NCOL + col];
        float v = -((asq + 2.0f * cross) + CSs[col]);   // reference grouping
        vs[j] = v;
        float g = gumbel_elem(fk0, fk1, ebase + (unsigned)k);
        float s = scale * v + g;
        if (s > bestS || (s == bestS && k < bestK)) { bestS = s; bestK = k; }
    }
    #pragma unroll
    for (int off = 16; off; off >>= 1) {
        float oS = __shfl_xor_sync(0xffffffffu, bestS, off);
        int   oK = __shfl_xor_sync(0xffffffffu, bestK, off);
        if (oS > bestS || (oS == bestS && oK < bestK)) { bestS = oS; bestK = oK; }
    }
    if (l == 0) d_idx[nxt][b * CB + c] = bestK;

    if (last) {
        float m = -INFINITY;
        #pragma unroll
        for (int j = 0; j < 8; j++) m = fmaxf(m, scale * vs[j]);
        #pragma unroll
        for (int off = 16; off; off >>= 1)
            m = fmaxf(m, __shfl_xor_sync(0xffffffffu, m, off));
        float se = 0.0f;
        #pragma unroll
        for (int j = 0; j < 8; j++) se += expf(scale * vs[j] - m);
        #pragma unroll
        for (int off = 16; off; off >>= 1)
            se += __shfl_xor_sync(0xffffffffu, se, off);
        float lse = m + logf(se);
        float H = 0.0f, ES = 0.0f;
        #pragma unroll
        for (int j = 0; j < 8; j++) {
            int k = l + 32 * j;
            float lp = scale * vs[j] - lse;
            float p = expf(lp);
            H  = fmaf(-p, lp, H);
            ES = fmaf(p, -vs[j], ES);
            d_Pb[(size_t)b * NCOL + c * KK + k] = p;
        }
        #pragma unroll
        for (int off = 16; off; off >>= 1) {
            H  += __shfl_xor_sync(0xffffffffu, H, off);
            ES += __shfl_xor_sync(0xffffffffu, ES, off);
        }
        if (l == 0) { d_Hb[b * CB + c] = H; d_ESb[b * CB + c] = ES; }
    }
}

// ---------------- last-iter column sums of probs (deterministic) ----------------
__global__ void colsum_k() {
    const int col = blockIdx.y * 256 + threadIdx.x;
    const int bx = blockIdx.x;             // 32 b-chunks of 512
    float s = 0.0f;
    for (int b = bx * 512; b < (bx + 1) * 512; b++)
        s += d_Pb[(size_t)b * NCOL + col];
    d_Pc[bx][col] = s;
}

// ---------------- outputs ----------------
__global__ void outidx_k(float* out, int out_size) {
    int t = blockIdx.x * blockDim.x + threadIdx.x;
    if (t < NIDX && t < out_size) out[t] = (float)d_idx[0][t];
}

__global__ void scal_k(float* out, int out_size) {
    const int t = threadIdx.x;
    __shared__ float sh[256];

    float v = 0.0f;
    for (int i = t; i < NXB; i += 256) v += d_xsqp[i];
    sh[t] = v; __syncthreads();
    for (int s = 128; s; s >>= 1) { if (t < s) sh[t] += sh[t + s]; __syncthreads(); }
    float xsq = sh[0]; __syncthreads();

    v = 0.0f;
    for (int i = t; i < NIDX; i += 256) v += d_Hb[i];
    sh[t] = v; __syncthreads();
    for (int s = 128; s; s >>= 1) { if (t < s) sh[t] += sh[t + s]; __syncthreads(); }
    float Hs = sh[0]; __syncthreads();

    v = 0.0f;
    for (int i = t; i < NIDX; i += 256) v += d_ESb[i];
    sh[t] = v; __syncthreads();
    for (int s = 128; s; s >>= 1) { if (t < s) sh[t] += sh[t + s]; __syncthreads(); }
    float ESs = sh[0]; __syncthreads();

    v = 0.0f;
    for (int col = t; col < NCOL; col += 256) {
        float s = 0.0f;
        #pragma unroll
        for (int bx = 0; bx < 32; bx++) s += d_Pc[bx][col];
        float avg = s / (float)BDIM;
        v += -avg * logf(avg + 1e-20f);
    }
    sh[t] = v; __syncthreads();
    for (int s = 128; s; s >>= 1) { if (t < s) sh[t] += sh[t + s]; __syncthreads(); }
    float cent = sh[0];

    if (t == 0 && out_size >= NIDX + 3) {
        out[NIDX + 0] = logf((float)KK) - cent / (float)CB;  // entropy_loss
        out[NIDX + 1] = Hs / (float)NIDX;                    // frame_entropy
        out[NIDX + 2] = (ESs / (float)CB) / (xsq + 1e-20f);  // reconstruction_loss
    }
}

// ---------------- launch ----------------
extern "C" void kernel_launch(void* const* d_in, const int* in_sizes, int n_in,
                              void* d_out, int out_size) {
    const float* x       = (const float*)d_in[0];
    const float* centers = (const float*)d_in[1];
    const float* fes     = (const float*)d_in[2];
    const int*   init_i  = (const int*)d_in[3];
    float* out = (float*)d_out;
    (void)in_sizes; (void)n_in;

    static int smem_set = 0;
    if (!smem_set) {
        cudaFuncSetAttribute(ref_k, cudaFuncAttributeMaxDynamicSharedMemorySize,
                             RSM_FLOATS * 4);
        cudaFuncSetAttribute(x0mma_k, cudaFuncAttributeMaxDynamicSharedMemorySize,
                             4 * 128 * XSTR * 4);
        smem_set = 1;
    }

    init_k<<<(NIDX + 255) / 256, 256>>>(init_i);
    censq_k<<<NCOL, 128>>>(centers);
    xsq_k<<<NXB, 256>>>(x);

    // one-time GEMMs: G2 = CF @ CF^T (fp32 scalar), X0 = x @ CF^T (3xTF32 mma)
    {
        float* G2p; cudaGetSymbolAddress((void**)&G2p, d_G2);
        float* X0p; cudaGetSymbolAddress((void**)&X0p, d_X0);
        dim3 gg(NCOL / 64, CB);
        gemm_k<<<gg, 256>>>(centers, centers, G2p);
        dim3 gx(BDIM / 128, NCOL / 128);
        x0mma_k<<<gx, 256, 4 * 128 * XSTR * 4>>>(x, centers, X0p);
    }

    for (int i = 0; i < 4; i++) {
        unsigned fk0 = 0u, fk1 = (unsigned)i;
        tf2x32(0u, 1234u, fk0, fk1);   // fold_in(key(1234), i)
        asq_k<<<BDIM, 256>>>(x, centers, i & 1);
        ref_k<<<BDIM, 256, RSM_FLOATS * 4>>>(fes, i & 1, (i + 1) & 1,
                                             (i == 3) ? 1 : 0, fk0, fk1);
    }

    {
        dim3 gc(32, CB);
        colsum_k<<<gc, 256>>>();
    }
    outidx_k<<<(NIDX + 255) / 256, 256>>>(out, out_size);
    scal_k<<<1, 256>>>(out, out_size);
}

// round 12
// speedup vs baseline: 1.2984x; 1.0170x over previous
#include <cuda_runtime.h>
#include <math.h>
#include <stdint.h>
#include <stddef.h>

#define BDIM 16384
#define CB   8
#define KK   256
#define DD   512
#define NCOL (CB*KK)              /* 2048 */
#define NIDX (BDIM*CB)            /* 131072 */
#define NXB  1024
#define XSTR 36                   /* smem row stride for mma tiles */
#define BCH  9216                 /* words per B chunk: Bh(4608)+Bl(4608) */

// ---------------- static device scratch (no allocations allowed) ----------------
static __device__ float d_X0[(size_t)BDIM*NCOL];   // x @ centers^T       (134MB)
static __device__ float d_G2[(size_t)NCOL*NCOL];   // centers @ centers^T (16MB)
static __device__ float d_Pb[(size_t)BDIM*NCOL];   // per-frame probs, last iter (134MB)
static __device__ __align__(16) uint32_t d_Bp[16*16*BCH]; // prepacked TF32 B tiles (9.4MB)
static __device__ float d_censq[NCOL];
static __device__ float d_asq[NIDX];
static __device__ int   d_idx[2][NIDX];
static __device__ float d_Hb[NIDX];
static __device__ float d_ESb[NIDX];
static __device__ float d_Pc[32][NCOL];
static __device__ float d_xsqp[NXB];

// ---------------- Threefry-2x32-20 (exact JAX semantics) ----------------
__host__ __device__ __forceinline__ unsigned rotl32(unsigned x, int r) {
    return (x << r) | (x >> (32 - r));
}
__host__ __device__ __forceinline__ void tf2x32(unsigned k0, unsigned k1,
                                                unsigned& x0, unsigned& x1) {
    unsigned k2 = k0 ^ k1 ^ 0x1BD11BDAu;
    x0 += k0; x1 += k1;
#define TFR(r) { x0 += x1; x1 = rotl32(x1, (r)); x1 ^= x0; }
    TFR(13) TFR(15) TFR(26) TFR(6)   x0 += k1; x1 += k2 + 1u;
    TFR(17) TFR(29) TFR(16) TFR(24)  x0 += k2; x1 += k0 + 2u;
    TFR(13) TFR(15) TFR(26) TFR(6)   x0 += k0; x1 += k1 + 3u;
    TFR(17) TFR(29) TFR(16) TFR(24)  x0 += k1; x1 += k2 + 4u;
    TFR(13) TFR(15) TFR(26) TFR(6)   x0 += k2; x1 += k0 + 5u;
#undef TFR
}

__device__ __forceinline__ float gumbel_from_bits(unsigned r) {
    float f = __uint_as_float((r >> 9) | 0x3f800000u) - 1.0f;
    float u = (f == 0.0f) ? 1.17549435e-38f : f;
    return -logf(-logf(u));
}

// jax_threefry_partitionable random_bits: elem e -> threefry(key,(0,e)), o0^o1
__device__ __forceinline__ float gumbel_elem(unsigned k0, unsigned k1, unsigned e) {
    unsigned x0 = 0u, x1 = e;
    tf2x32(k0, k1, x0, x1);
    return gumbel_from_bits(x0 ^ x1);
}

// ---------------- cp.async + mma helpers ----------------
__device__ __forceinline__ uint32_t smem_u32(const void* p) {
    uint32_t a;
    asm("{ .reg .u64 t; cvta.to.shared.u64 t, %1; cvt.u32.u64 %0, t; }" : "=r"(a) : "l"(p));
    return a;
}
#define CP_ASYNC16(d, s) asm volatile("cp.async.cg.shared.global [%0], [%1], 16;" :: "r"(d), "l"(s) : "memory")
#define CP_COMMIT()      asm volatile("cp.async.commit_group;" ::: "memory")
#define CP_WAIT0()       asm volatile("cp.async.wait_group 0;" ::: "memory")
#define CP_WAIT1()       asm volatile("cp.async.wait_group 1;" ::: "memory")

__device__ __forceinline__ uint32_t to_tf32(float v) {
    uint32_t r;
    asm("cvt.rna.tf32.f32 %0, %1;" : "=r"(r) : "f"(v));
    return r;
}
__device__ __forceinline__ void mma_tf32(float* c, const uint32_t* a,
                                         uint32_t b0, uint32_t b1) {
    asm volatile(
        "mma.sync.aligned.m16n8k8.row.col.f32.tf32.tf32.f32 "
        "{%0,%1,%2,%3}, {%4,%5,%6,%7}, {%8,%9}, {%0,%1,%2,%3};"
        : "+f"(c[0]), "+f"(c[1]), "+f"(c[2]), "+f"(c[3])
        : "r"(a[0]), "r"(a[1]), "r"(a[2]), "r"(a[3]), "r"(b0), "r"(b1));
}

// ---------------- small kernels ----------------
__global__ void init_k(const int* __restrict__ init_idx) {
    int t = blockIdx.x * blockDim.x + threadIdx.x;
    if (t < NIDX) d_idx[0][t] = init_idx[t];
}

__global__ void censq_k(const float* __restrict__ centers) {
    int row = blockIdx.x;                  // 0..2047
    const float* cc = centers + (size_t)row * DD;
    float p = 0.0f;
    for (int d = threadIdx.x; d < DD; d += 128) p = fmaf(cc[d], cc[d], p);
    #pragma unroll
    for (int off = 16; off; off >>= 1) p += __shfl_xor_sync(0xffffffffu, p, off);
    __shared__ float red[4];
    if ((threadIdx.x & 31) == 0) red[threadIdx.x >> 5] = p;
    __syncthreads();
    if (threadIdx.x == 0) d_censq[row] = ((red[0] + red[1]) + (red[2] + red[3]));
}

__global__ void xsq_k(const float* __restrict__ x) {
    const size_t N = (size_t)BDIM * DD;
    float p = 0.0f;
    for (size_t i = (size_t)blockIdx.x * blockDim.x + threadIdx.x; i < N;
         i += (size_t)gridDim.x * blockDim.x)
        p = fmaf(x[i], x[i], p);
    #pragma unroll
    for (int off = 16; off; off >>= 1) p += __shfl_xor_sync(0xffffffffu, p, off);
    __shared__ float red[8];
    if ((threadIdx.x & 31) == 0) red[threadIdx.x >> 5] = p;
    __syncthreads();
    if (threadIdx.x == 0) {
        float s = 0.0f;
        #pragma unroll
        for (int w = 0; w < 8; w++) s += red[w];
        d_xsqp[blockIdx.x] = s;
    }
}

// ---------------- prepack centers into TF32 hi/lo tiles (smem-layout, padded) ----------------
__global__ void bprep_k(const float* __restrict__ centers) {
    unsigned t = blockIdx.x * blockDim.x + threadIdx.x;   // < 2048*512
    unsigned n = t >> 9, d = t & 511;
    float v = centers[(size_t)n * DD + d];
    uint32_t hi = to_tf32(v);
    uint32_t lo = to_tf32(v - __uint_as_float(hi));
    unsigned nblk = n >> 7, row = n & 127, kc = d >> 5, col = d & 31;
    unsigned base = (nblk * 16 + kc) * BCH;
    d_Bp[base + row * XSTR + col] = hi;
    d_Bp[base + 4608 + row * XSTR + col] = lo;
}

// ---------------- scalar SGEMM (round-7, proven; used for G2 only) ----------------
__global__ __launch_bounds__(256, 2)
void gemm_k(const float* __restrict__ A, const float* __restrict__ centers,
            float* __restrict__ out) {
    __shared__ float As[16][68];
    __shared__ float Bs[16][256];
    const int tid = threadIdx.x;
    const int w = tid >> 5, l = tid & 31;
    const int cy = blockIdx.y;
    const int r0 = blockIdx.x * 64;

    const int lr = tid >> 2, lq = tid & 3;
    const float* aP = A + (size_t)(r0 + lr) * DD + lq * 4;
    const int bk = tid >> 1, bd = (tid & 1) * 8;
    const float* b0P = centers + ((size_t)cy * KK + bk) * DD + bd;
    const float* b1P = centers + ((size_t)cy * KK + 128 + bk) * DD + bd;

    float acc[8][8];
    #pragma unroll
    for (int i = 0; i < 8; i++)
        #pragma unroll
        for (int j = 0; j < 8; j++) acc[i][j] = 0.0f;

    float4 a4 = *(const float4*)(aP);
    float4 q0 = *(const float4*)(b0P);
    float4 q1 = *(const float4*)(b0P + 4);
    float4 q2 = *(const float4*)(b1P);
    float4 q3 = *(const float4*)(b1P + 4);

    for (int kb = 0; kb < 32; kb++) {
        __syncthreads();
        As[lq*4+0][lr] = a4.x; As[lq*4+1][lr] = a4.y;
        As[lq*4+2][lr] = a4.z; As[lq*4+3][lr] = a4.w;
        Bs[bd+0][bk] = q0.x; Bs[bd+1][bk] = q0.y;
        Bs[bd+2][bk] = q0.z; Bs[bd+3][bk] = q0.w;
        Bs[bd+4][bk] = q1.x; Bs[bd+5][bk] = q1.y;
        Bs[bd+6][bk] = q1.z; Bs[bd+7][bk] = q1.w;
        Bs[bd+0][128+bk] = q2.x; Bs[bd+1][128+bk] = q2.y;
        Bs[bd+2][128+bk] = q2.z; Bs[bd+3][128+bk] = q2.w;
        Bs[bd+4][128+bk] = q3.x; Bs[bd+5][128+bk] = q3.y;
        Bs[bd+6][128+bk] = q3.z; Bs[bd+7][128+bk] = q3.w;
        __syncthreads();
        if (kb < 31) {
            const int d0 = (kb + 1) * 16;
            a4 = *(const float4*)(aP + d0);
            q0 = *(const float4*)(b0P + d0);
            q1 = *(const float4*)(b0P + d0 + 4);
            q2 = *(const float4*)(b1P + d0);
            q3 = *(const float4*)(b1P + d0 + 4);
        }
        #pragma unroll
        for (int d = 0; d < 16; d++) {
            float4 a0 = *(const float4*)&As[d][w*8];
            float4 a1 = *(const float4*)&As[d][w*8+4];
            float4 bb0 = *(const float4*)&Bs[d][l*8];
            float4 bb1 = *(const float4*)&Bs[d][l*8+4];
            float av[8] = {a0.x,a0.y,a0.z,a0.w,a1.x,a1.y,a1.z,a1.w};
            float bv[8] = {bb0.x,bb0.y,bb0.z,bb0.w,bb1.x,bb1.y,bb1.z,bb1.w};
            #pragma unroll
            for (int i = 0; i < 8; i++)
                #pragma unroll
                for (int j = 0; j < 8; j++)
                    acc[i][j] = fmaf(av[i], bv[j], acc[i][j]);
        }
    }

    #pragma unroll
    for (int i = 0; i < 8; i++) {
        float* o = out + (size_t)(r0 + w*8 + i) * NCOL + cy * KK + l * 8;
        float4 v0 = make_float4(acc[i][0], acc[i][1], acc[i][2], acc[i][3]);
        float4 v1 = make_float4(acc[i][4], acc[i][5], acc[i][6], acc[i][7]);
        *(float4*)o = v0;
        *(float4*)(o + 4) = v1;
    }
}

// ---------------- X0 GEMM on tensor cores: 3xTF32 mma.sync, pipelined ----------------
// Math identical to round 11 (same conversions, same MMA order) -> bit-identical X0.
// New: B tiles prepacked in global (cp.async straight in, double-buffered);
// A global loads register-prefetched one chunk ahead.
__global__ __launch_bounds__(256, 2)
void x0mma_k(const float* __restrict__ A, float* __restrict__ out) {
    extern __shared__ uint32_t xsm[];
    uint32_t* Ah  = xsm;                      // [128][XSTR]
    uint32_t* Al  = xsm + 4608;
    uint32_t* Bst = xsm + 2 * 4608;           // 2 stages x BCH (Bh | Bl)

    const int tid  = threadIdx.x;
    const int warp = tid >> 5, lane = tid & 31;
    const int g = lane >> 2, tg = lane & 3;
    const int mw = warp >> 2, nw = warp & 3;   // warp tile (mw*64, nw*32)
    const int r0 = blockIdx.x * 128;
    const uint32_t* gB = d_Bp + (size_t)blockIdx.y * 16 * BCH;

    float acc[4][4][4];
    #pragma unroll
    for (int i = 0; i < 4; i++)
        #pragma unroll
        for (int j = 0; j < 4; j++)
            #pragma unroll
            for (int q = 0; q < 4; q++) acc[i][j][q] = 0.0f;

    const int lrow = tid >> 3;              // 0..31
    const int lkq  = (tid & 7) * 4;         // k offset 0,4,..28

    // prologue: A chunk 0 into regs, B chunk 0 via cp.async
    float4 av4[4];
    #pragma unroll
    for (int q = 0; q < 4; q++)
        av4[q] = *(const float4*)(A + (size_t)(r0 + q * 32 + lrow) * DD + lkq);
    {
        const float4* src = (const float4*)(gB);
        uint32_t dst = smem_u32(Bst);
        #pragma unroll
        for (int i = 0; i < 9; i++)
            CP_ASYNC16(dst + (uint32_t)(tid + i * 256) * 16, src + tid + i * 256);
        CP_COMMIT();
    }

    for (int kc = 0; kc < 16; kc++) {
        const int s = kc & 1;
        // convert A chunk kc (registers)
        uint4 hv[4], lv[4];
        #pragma unroll
        for (int q = 0; q < 4; q++) {
            float4 v = av4[q];
            uint32_t h0 = to_tf32(v.x), h1 = to_tf32(v.y),
                     h2 = to_tf32(v.z), h3 = to_tf32(v.w);
            hv[q] = make_uint4(h0, h1, h2, h3);
            lv[q] = make_uint4(to_tf32(v.x - __uint_as_float(h0)),
                               to_tf32(v.y - __uint_as_float(h1)),
                               to_tf32(v.z - __uint_as_float(h2)),
                               to_tf32(v.w - __uint_as_float(h3)));
        }
        __syncthreads();   // all threads done with MMAs of kc-1 (A smem + stage s^1 free)
        #pragma unroll
        for (int q = 0; q < 4; q++) {
            int m = q * 32 + lrow;
            *(uint4*)&Ah[m * XSTR + lkq] = hv[q];
            *(uint4*)&Al[m * XSTR + lkq] = lv[q];
        }
        if (kc < 15) {
            // B chunk kc+1 into the other stage (overlaps MMAs below)
            const float4* src = (const float4*)(gB + (kc + 1) * BCH);
            uint32_t dst = smem_u32(Bst + (s ^ 1) * BCH);
            #pragma unroll
            for (int i = 0; i < 9; i++)
                CP_ASYNC16(dst + (uint32_t)(tid + i * 256) * 16, src + tid + i * 256);
            CP_COMMIT();
            // A chunk kc+1 into regs (LDG latency hidden by MMAs below)
            #pragma unroll
            for (int q = 0; q < 4; q++)
                av4[q] = *(const float4*)(A + (size_t)(r0 + q * 32 + lrow) * DD
                                          + (kc + 1) * 32 + lkq);
            CP_WAIT1();    // chunk kc arrived (kc+1 still in flight)
        } else {
            CP_WAIT0();
        }
        __syncthreads();

        const uint32_t* Bh = Bst + s * BCH;
        const uint32_t* Bl = Bh + 4608;
        #pragma unroll
        for (int ka = 0; ka < 4; ka++) {
            const int kb = ka * 8;
            uint32_t bh0[4], bh1[4], bl0[4], bl1[4];
            #pragma unroll
            for (int j = 0; j < 4; j++) {
                int nn = nw * 32 + j * 8 + g;
                bh0[j] = Bh[nn * XSTR + kb + tg];
                bh1[j] = Bh[nn * XSTR + kb + tg + 4];
                bl0[j] = Bl[nn * XSTR + kb + tg];
                bl1[j] = Bl[nn * XSTR + kb + tg + 4];
            }
            #pragma unroll
            for (int i = 0; i < 4; i++) {
                int mm = mw * 64 + i * 16;
                uint32_t ah[4], al[4];
                ah[0] = Ah[(mm + g) * XSTR + kb + tg];
                ah[1] = Ah[(mm + g + 8) * XSTR + kb + tg];
                ah[2] = Ah[(mm + g) * XSTR + kb + tg + 4];
                ah[3] = Ah[(mm + g + 8) * XSTR + kb + tg + 4];
                al[0] = Al[(mm + g) * XSTR + kb + tg];
                al[1] = Al[(mm + g + 8) * XSTR + kb + tg];
                al[2] = Al[(mm + g) * XSTR + kb + tg + 4];
                al[3] = Al[(mm + g + 8) * XSTR + kb + tg + 4];
                #pragma unroll
                for (int j = 0; j < 4; j++) {
                    mma_tf32(acc[i][j], ah, bl0[j], bl1[j]);
                    mma_tf32(acc[i][j], al, bh0[j], bh1[j]);
                    mma_tf32(acc[i][j], ah, bh0[j], bh1[j]);
                }
            }
        }
    }

    const int n0 = blockIdx.y * 128;
    #pragma unroll
    for (int i = 0; i < 4; i++) {
        int m0 = r0 + mw * 64 + i * 16;
        #pragma unroll
        for (int j = 0; j < 4; j++) {
            int n = n0 + nw * 32 + j * 8 + tg * 2;
            *(float2*)(out + (size_t)(m0 + g) * NCOL + n) =
                make_float2(acc[i][j][0], acc[i][j][1]);
            *(float2*)(out + (size_t)(m0 + g + 8) * NCOL + n) =
                make_float2(acc[i][j][2], acc[i][j][3]);
        }
    }
}

// ---------------- per-iteration a_sq ----------------
__global__ __launch_bounds__(256)
void asq_k(const float* __restrict__ x, const float* __restrict__ centers, int cur) {
    __shared__ float cens[CB][DD];
    __shared__ float xe[DD];
    __shared__ int ids[CB];
    const int b = blockIdx.x, tid = threadIdx.x;
    const int w = tid >> 5, l = tid & 31;
    if (tid < CB) ids[tid] = d_idx[cur][b * CB + tid];
    __syncthreads();
    for (int t = tid; t < CB * DD; t += 256) {
        int c = t >> 9, d = t & 511;
        cens[c][d] = centers[((size_t)c * KK + ids[c]) * DD + d];
    }
    __syncthreads();
    #pragma unroll
    for (int q = 0; q < 2; q++) {
        int d = tid + q * 256;
        float s = 0.0f;
        #pragma unroll
        for (int c = 0; c < CB; c++) s += cens[c][d];
        xe[d] = s - x[(size_t)b * DD + d];
    }
    __syncthreads();
    float p = 0.0f;
    #pragma unroll
    for (int it = 0; it < 16; it++) {
        int d = l + it * 32;
        float a = xe[d] - cens[w][d];
        p = fmaf(a, a, p);
    }
    #pragma unroll
    for (int off = 16; off; off >>= 1) p += __shfl_xor_sync(0xffffffffu, p, off);
    if (l == 0) d_asq[b * CB + w] = p;
}

// ---------------- fused refine: gather + combine + gumbel-argmax + stats ----------------
#define RSM_FLOATS (8*NCOL + 3*NCOL)
__global__ void __launch_bounds__(256)
ref_k(const float* __restrict__ fes, int cur, int nxt, int last,
      unsigned fk0, unsigned fk1) {
    extern __shared__ float sm[];
    float* G2s = sm;                 // 8 rows
    float* X0s = sm + 8 * NCOL;
    float* CSs = sm + 9 * NCOL;
    float* Ss  = sm + 10 * NCOL;
    __shared__ int ids[CB];

    const int tid = threadIdx.x;
    const int w = tid >> 5, l = tid & 31;
    const int b = blockIdx.x;

    if (tid < CB) ids[tid] = d_idx[cur][b * CB + tid];
    __syncthreads();

    {
        #pragma unroll
        for (int c = 0; c < CB; c++) {
            const float4* src = (const float4*)(d_G2 + (size_t)(c * KK + ids[c]) * NCOL);
            uint32_t dst = smem_u32(G2s + c * NCOL);
            CP_ASYNC16(dst + tid * 16, src + tid);
            CP_ASYNC16(dst + (tid + 256) * 16, src + tid + 256);
        }
        const float4* sx = (const float4*)(d_X0 + (size_t)b * NCOL);
        uint32_t dx = smem_u32(X0s);
        CP_ASYNC16(dx + tid * 16, sx + tid);
        CP_ASYNC16(dx + (tid + 256) * 16, sx + tid + 256);
        const float4* sc = (const float4*)(d_censq);
        uint32_t dc = smem_u32(CSs);
        CP_ASYNC16(dc + tid * 16, sc + tid);
        CP_ASYNC16(dc + (tid + 256) * 16, sc + tid + 256);
        CP_COMMIT();
        CP_WAIT0();
    }
    __syncthreads();

    #pragma unroll
    for (int q = 0; q < 8; q++) {
        int col = tid + q * 256;
        float s = 0.0f;
        #pragma unroll
        for (int c = 0; c < CB; c++) s += G2s[c * NCOL + col];
        Ss[col] = s;
    }
    __syncthreads();

    const int c = w;
    const float asq = d_asq[b * CB + c];
    const float scale = expf(fes[0]);
    const unsigned ebase = ((unsigned)(b * CB + c)) << 8;

    float vs[8];
    float bestS = -INFINITY; int bestK = 0;
    #pragma unroll
    for (int j = 0; j < 8; j++) {
        int k = l + 32 * j;
        int col = c * KK + k;
        float cross = (Ss[col] - X0s[col]) - G2s[c * NCOL + col];
        float v = -((asq + 2.0f * cross) + CSs[col]);   // reference grouping
        vs[j] = v;
        float g = gumbel_elem(fk0, fk1, ebase + (unsigned)k);
        float s = scale * v + g;
        if (s > bestS || (s == bestS && k < bestK)) { bestS = s; bestK = k; }
    }
    #pragma unroll
    for (int off = 16; off; off >>= 1) {
        float oS = __shfl_xor_sync(0xffffffffu, bestS, off);
        int   oK = __shfl_xor_sync(0xffffffffu, bestK, off);
        if (oS > bestS || (oS == bestS && oK < bestK)) { bestS = oS; bestK = oK; }
    }
    if (l == 0) d_idx[nxt][b * CB + c] = bestK;

    if (last) {
        float m = -INFINITY;
        #pragma unroll
        for (int j = 0; j < 8; j++) m = fmaxf(m, scale * vs[j]);
        #pragma unroll
        for (int off = 16; off; off >>= 1)
            m = fmaxf(m, __shfl_xor_sync(0xffffffffu, m, off));
        float se = 0.0f;
        #pragma unroll
        for (int j = 0; j < 8; j++) se += expf(scale * vs[j] - m);
        #pragma unroll
        for (int off = 16; off; off >>= 1)
            se += __shfl_xor_sync(0xffffffffu, se, off);
        float lse = m + logf(se);
        float H = 0.0f, ES = 0.0f;
        #pragma unroll
        for (int j = 0; j < 8; j++) {
            int k = l + 32 * j;
            float lp = scale * vs[j] - lse;
            float p = expf(lp);
            H  = fmaf(-p, lp, H);
            ES = fmaf(p, -vs[j], ES);
            d_Pb[(size_t)b * NCOL + c * KK + k] = p;
        }
        #pragma unroll
        for (int off = 16; off; off >>= 1) {
            H  += __shfl_xor_sync(0xffffffffu, H, off);
            ES += __shfl_xor_sync(0xffffffffu, ES, off);
        }
        if (l == 0) { d_Hb[b * CB + c] = H; d_ESb[b * CB + c] = ES; }
    }
}

// ---------------- last-iter column sums of probs (deterministic) ----------------
__global__ void colsum_k() {
    const int col = blockIdx.y * 256 + threadIdx.x;
    const int bx = blockIdx.x;             // 32 b-chunks of 512
    float s = 0.0f;
    for (int b = bx * 512; b < (bx + 1) * 512; b++)
        s += d_Pb[(size_t)b * NCOL + col];
    d_Pc[bx][col] = s;
}

// ---------------- outputs ----------------
__global__ void outidx_k(float* out, int out_size) {
    int t = blockIdx.x * blockDim.x + threadIdx.x;
    if (t < NIDX && t < out_size) out[t] = (float)d_idx[0][t];
}

__global__ void scal_k(float* out, int out_size) {
    const int t = threadIdx.x;
    __shared__ float sh[256];

    float v = 0.0f;
    for (int i = t; i < NXB; i += 256) v += d_xsqp[i];
    sh[t] = v; __syncthreads();
    for (int s = 128; s; s >>= 1) { if (t < s) sh[t] += sh[t + s]; __syncthreads(); }
    float xsq = sh[0]; __syncthreads();

    v = 0.0f;
    for (int i = t; i < NIDX; i += 256) v += d_Hb[i];
    sh[t] = v; __syncthreads();
    for (int s = 128; s; s >>= 1) { if (t < s) sh[t] += sh[t + s]; __syncthreads(); }
    float Hs = sh[0]; __syncthreads();

    v = 0.0f;
    for (int i = t; i < NIDX; i += 256) v += d_ESb[i];
    sh[t] = v; __syncthreads();
    for (int s = 128; s; s >>= 1) { if (t < s) sh[t] += sh[t + s]; __syncthreads(); }
    float ESs = sh[0]; __syncthreads();

    v = 0.0f;
    for (int col = t; col < NCOL; col += 256) {
        float s = 0.0f;
        #pragma unroll
        for (int bx = 0; bx < 32; bx++) s += d_Pc[bx][col];
        float avg = s / (float)BDIM;
        v += -avg * logf(avg + 1e-20f);
    }
    sh[t] = v; __syncthreads();
    for (int s = 128; s; s >>= 1) { if (t < s) sh[t] += sh[t + s]; __syncthreads(); }
    float cent = sh[0];

    if (t == 0 && out_size >= NIDX + 3) {
        out[NIDX + 0] = logf((float)KK) - cent / (float)CB;  // entropy_loss
        out[NIDX + 1] = Hs / (float)NIDX;                    // frame_entropy
        out[NIDX + 2] = (ESs / (float)CB) / (xsq + 1e-20f);  // reconstruction_loss
    }
}

// ---------------- launch ----------------
extern "C" void kernel_launch(void* const* d_in, const int* in_sizes, int n_in,
                              void* d_out, int out_size) {
    const float* x       = (const float*)d_in[0];
    const float* centers = (const float*)d_in[1];
    const float* fes     = (const float*)d_in[2];
    const int*   init_i  = (const int*)d_in[3];
    float* out = (float*)d_out;
    (void)in_sizes; (void)n_in;

    static int smem_set = 0;
    if (!smem_set) {
        cudaFuncSetAttribute(ref_k, cudaFuncAttributeMaxDynamicSharedMemorySize,
                             RSM_FLOATS * 4);
        cudaFuncSetAttribute(x0mma_k, cudaFuncAttributeMaxDynamicSharedMemorySize,
                             (2 * 4608 + 2 * BCH) * 4);
        smem_set = 1;
    }

    init_k<<<(NIDX + 255) / 256, 256>>>(init_i);
    censq_k<<<NCOL, 128>>>(centers);
    xsq_k<<<NXB, 256>>>(x);
    bprep_k<<<(NCOL * DD) / 256, 256>>>(centers);

    // one-time GEMMs: G2 = CF @ CF^T (fp32 scalar), X0 = x @ CF^T (3xTF32 mma)
    {
        float* G2p; cudaGetSymbolAddress((void**)&G2p, d_G2);
        float* X0p; cudaGetSymbolAddress((void**)&X0p, d_X0);
        dim3 gg(NCOL / 64, CB);
        gemm_k<<<gg, 256>>>(centers, centers, G2p);
        dim3 gx(BDIM / 128, NCOL / 128);
        x0mma_k<<<gx, 256, (2 * 4608 + 2 * BCH) * 4>>>(x, X0p);
    }

    for (int i = 0; i < 4; i++) {
        unsigned fk0 = 0u, fk1 = (unsigned)i;
        tf2x32(0u, 1234u, fk0, fk1);   // fold_in(key(1234), i)
        asq_k<<<BDIM, 256>>>(x, centers, i & 1);
        ref_k<<<BDIM, 256, RSM_FLOATS * 4>>>(fes, i & 1, (i + 1) & 1,
                                             (i == 3) ? 1 : 0, fk0, fk1);
    }

    {
        dim3 gc(32, CB);
        colsum_k<<<gc, 256>>>();
    }
    outidx_k<<<(NIDX + 255) / 256, 256>>>(out, out_size);
    scal_k<<<1, 256>>>(out, out_size);
}

// round 13
// speedup vs baseline: 1.4378x; 1.1074x over previous
#include <cuda_runtime.h>
#include <math.h>
#include <stdint.h>
#include <stddef.h>

#define BDIM 16384
#define CB   8
#define KK   256
#define DD   512
#define NCOL (CB*KK)              /* 2048 */
#define NIDX (BDIM*CB)            /* 131072 */
#define NXB  1024
#define XSTR 36                   /* smem row stride for mma tiles */
#define BCH  9216                 /* words per B chunk: Bh(4608)+Bl(4608) */

// ---------------- static device scratch (no allocations allowed) ----------------
static __device__ float d_X0[(size_t)BDIM*NCOL];   // x @ centers^T       (134MB)
static __device__ float d_G2[(size_t)NCOL*NCOL];   // centers @ centers^T (16MB)
static __device__ float d_Pb[(size_t)BDIM*NCOL];   // per-frame probs, last iter (134MB)
static __device__ __align__(16) uint32_t d_Bp[16*16*BCH]; // prepacked TF32 B tiles (9.4MB)
static __device__ float d_censq[NCOL];
static __device__ int   d_idx[2][NIDX];
static __device__ float d_Hb[NIDX];
static __device__ float d_ESb[NIDX];
static __device__ float d_Pc[32][NCOL];
static __device__ float d_xsqp[NXB];

// ---------------- Threefry-2x32-20 (exact JAX semantics) ----------------
__host__ __device__ __forceinline__ unsigned rotl32(unsigned x, int r) {
    return (x << r) | (x >> (32 - r));
}
__host__ __device__ __forceinline__ void tf2x32(unsigned k0, unsigned k1,
                                                unsigned& x0, unsigned& x1) {
    unsigned k2 = k0 ^ k1 ^ 0x1BD11BDAu;
    x0 += k0; x1 += k1;
#define TFR(r) { x0 += x1; x1 = rotl32(x1, (r)); x1 ^= x0; }
    TFR(13) TFR(15) TFR(26) TFR(6)   x0 += k1; x1 += k2 + 1u;
    TFR(17) TFR(29) TFR(16) TFR(24)  x0 += k2; x1 += k0 + 2u;
    TFR(13) TFR(15) TFR(26) TFR(6)   x0 += k0; x1 += k1 + 3u;
    TFR(17) TFR(29) TFR(16) TFR(24)  x0 += k1; x1 += k2 + 4u;
    TFR(13) TFR(15) TFR(26) TFR(6)   x0 += k2; x1 += k0 + 5u;
#undef TFR
}

__device__ __forceinline__ float gumbel_from_bits(unsigned r) {
    float f = __uint_as_float((r >> 9) | 0x3f800000u) - 1.0f;
    float u = (f == 0.0f) ? 1.17549435e-38f : f;
    return -logf(-logf(u));
}

// jax_threefry_partitionable random_bits: elem e -> threefry(key,(0,e)), o0^o1
__device__ __forceinline__ float gumbel_elem(unsigned k0, unsigned k1, unsigned e) {
    unsigned x0 = 0u, x1 = e;
    tf2x32(k0, k1, x0, x1);
    return gumbel_from_bits(x0 ^ x1);
}

// ---------------- cp.async + mma helpers ----------------
__device__ __forceinline__ uint32_t smem_u32(const void* p) {
    uint32_t a;
    asm("{ .reg .u64 t; cvta.to.shared.u64 t, %1; cvt.u32.u64 %0, t; }" : "=r"(a) : "l"(p));
    return a;
}
#define CP_ASYNC16(d, s) asm volatile("cp.async.cg.shared.global [%0], [%1], 16;" :: "r"(d), "l"(s) : "memory")
#define CP_COMMIT()      asm volatile("cp.async.commit_group;" ::: "memory")
#define CP_WAIT0()       asm volatile("cp.async.wait_group 0;" ::: "memory")
#define CP_WAIT1()       asm volatile("cp.async.wait_group 1;" ::: "memory")

__device__ __forceinline__ uint32_t to_tf32(float v) {
    uint32_t r;
    asm("cvt.rna.tf32.f32 %0, %1;" : "=r"(r) : "f"(v));
    return r;
}
__device__ __forceinline__ void mma_tf32(float* c, const uint32_t* a,
                                         uint32_t b0, uint32_t b1) {
    asm volatile(
        "mma.sync.aligned.m16n8k8.row.col.f32.tf32.tf32.f32 "
        "{%0,%1,%2,%3}, {%4,%5,%6,%7}, {%8,%9}, {%0,%1,%2,%3};"
        : "+f"(c[0]), "+f"(c[1]), "+f"(c[2]), "+f"(c[3])
        : "r"(a[0]), "r"(a[1]), "r"(a[2]), "r"(a[3]), "r"(b0), "r"(b1));
}

// ---------------- small kernels ----------------
__global__ void censq_k(const float* __restrict__ centers) {
    int row = blockIdx.x;                  // 0..2047
    const float* cc = centers + (size_t)row * DD;
    float p = 0.0f;
    for (int d = threadIdx.x; d < DD; d += 128) p = fmaf(cc[d], cc[d], p);
    #pragma unroll
    for (int off = 16; off; off >>= 1) p += __shfl_xor_sync(0xffffffffu, p, off);
    __shared__ float red[4];
    if ((threadIdx.x & 31) == 0) red[threadIdx.x >> 5] = p;
    __syncthreads();
    if (threadIdx.x == 0) d_censq[row] = ((red[0] + red[1]) + (red[2] + red[3]));
}

__global__ void xsq_k(const float* __restrict__ x) {
    const size_t N = (size_t)BDIM * DD;
    float p = 0.0f;
    for (size_t i = (size_t)blockIdx.x * blockDim.x + threadIdx.x; i < N;
         i += (size_t)gridDim.x * blockDim.x)
        p = fmaf(x[i], x[i], p);
    #pragma unroll
    for (int off = 16; off; off >>= 1) p += __shfl_xor_sync(0xffffffffu, p, off);
    __shared__ float red[8];
    if ((threadIdx.x & 31) == 0) red[threadIdx.x >> 5] = p;
    __syncthreads();
    if (threadIdx.x == 0) {
        float s = 0.0f;
        #pragma unroll
        for (int w = 0; w < 8; w++) s += red[w];
        d_xsqp[blockIdx.x] = s;
    }
}

// ---------------- prepack centers into TF32 hi/lo tiles (smem-layout, padded) ----------------
__global__ void bprep_k(const float* __restrict__ centers) {
    unsigned t = blockIdx.x * blockDim.x + threadIdx.x;   // < 2048*512
    unsigned n = t >> 9, d = t & 511;
    float v = centers[(size_t)n * DD + d];
    uint32_t hi = to_tf32(v);
    uint32_t lo = to_tf32(v - __uint_as_float(hi));
    unsigned nblk = n >> 7, row = n & 127, kc = d >> 5, col = d & 31;
    unsigned base = (nblk * 16 + kc) * BCH;
    d_Bp[base + row * XSTR + col] = hi;
    d_Bp[base + 4608 + row * XSTR + col] = lo;
}

// ---------------- scalar SGEMM (round-7, proven; used for G2 only) ----------------
__global__ __launch_bounds__(256, 2)
void gemm_k(const float* __restrict__ A, const float* __restrict__ centers,
            float* __restrict__ out) {
    __shared__ float As[16][68];
    __shared__ float Bs[16][256];
    const int tid = threadIdx.x;
    const int w = tid >> 5, l = tid & 31;
    const int cy = blockIdx.y;
    const int r0 = blockIdx.x * 64;

    const int lr = tid >> 2, lq = tid & 3;
    const float* aP = A + (size_t)(r0 + lr) * DD + lq * 4;
    const int bk = tid >> 1, bd = (tid & 1) * 8;
    const float* b0P = centers + ((size_t)cy * KK + bk) * DD + bd;
    const float* b1P = centers + ((size_t)cy * KK + 128 + bk) * DD + bd;

    float acc[8][8];
    #pragma unroll
    for (int i = 0; i < 8; i++)
        #pragma unroll
        for (int j = 0; j < 8; j++) acc[i][j] = 0.0f;

    float4 a4 = *(const float4*)(aP);
    float4 q0 = *(const float4*)(b0P);
    float4 q1 = *(const float4*)(b0P + 4);
    float4 q2 = *(const float4*)(b1P);
    float4 q3 = *(const float4*)(b1P + 4);

    for (int kb = 0; kb < 32; kb++) {
        __syncthreads();
        As[lq*4+0][lr] = a4.x; As[lq*4+1][lr] = a4.y;
        As[lq*4+2][lr] = a4.z; As[lq*4+3][lr] = a4.w;
        Bs[bd+0][bk] = q0.x; Bs[bd+1][bk] = q0.y;
        Bs[bd+2][bk] = q0.z; Bs[bd+3][bk] = q0.w;
        Bs[bd+4][bk] = q1.x; Bs[bd+5][bk] = q1.y;
        Bs[bd+6][bk] = q1.z; Bs[bd+7][bk] = q1.w;
        Bs[bd+0][128+bk] = q2.x; Bs[bd+1][128+bk] = q2.y;
        Bs[bd+2][128+bk] = q2.z; Bs[bd+3][128+bk] = q2.w;
        Bs[bd+4][128+bk] = q3.x; Bs[bd+5][128+bk] = q3.y;
        Bs[bd+6][128+bk] = q3.z; Bs[bd+7][128+bk] = q3.w;
        __syncthreads();
        if (kb < 31) {
            const int d0 = (kb + 1) * 16;
            a4 = *(const float4*)(aP + d0);
            q0 = *(const float4*)(b0P + d0);
            q1 = *(const float4*)(b0P + d0 + 4);
            q2 = *(const float4*)(b1P + d0);
            q3 = *(const float4*)(b1P + d0 + 4);
        }
        #pragma unroll
        for (int d = 0; d < 16; d++) {
            float4 a0 = *(const float4*)&As[d][w*8];
            float4 a1 = *(const float4*)&As[d][w*8+4];
            float4 bb0 = *(const float4*)&Bs[d][l*8];
            float4 bb1 = *(const float4*)&Bs[d][l*8+4];
            float av[8] = {a0.x,a0.y,a0.z,a0.w,a1.x,a1.y,a1.z,a1.w};
            float bv[8] = {bb0.x,bb0.y,bb0.z,bb0.w,bb1.x,bb1.y,bb1.z,bb1.w};
            #pragma unroll
            for (int i = 0; i < 8; i++)
                #pragma unroll
                for (int j = 0; j < 8; j++)
                    acc[i][j] = fmaf(av[i], bv[j], acc[i][j]);
        }
    }

    #pragma unroll
    for (int i = 0; i < 8; i++) {
        float* o = out + (size_t)(r0 + w*8 + i) * NCOL + cy * KK + l * 8;
        float4 v0 = make_float4(acc[i][0], acc[i][1], acc[i][2], acc[i][3]);
        float4 v1 = make_float4(acc[i][4], acc[i][5], acc[i][6], acc[i][7]);
        *(float4*)o = v0;
        *(float4*)(o + 4) = v1;
    }
}

// ---------------- X0 GEMM on tensor cores: 3xTF32 mma.sync, pipelined (round-12) ----------------
__global__ __launch_bounds__(256, 2)
void x0mma_k(const float* __restrict__ A, float* __restrict__ out) {
    extern __shared__ uint32_t xsm[];
    uint32_t* Ah  = xsm;                      // [128][XSTR]
    uint32_t* Al  = xsm + 4608;
    uint32_t* Bst = xsm + 2 * 4608;           // 2 stages x BCH (Bh | Bl)

    const int tid  = threadIdx.x;
    const int warp = tid >> 5, lane = tid & 31;
    const int g = lane >> 2, tg = lane & 3;
    const int mw = warp >> 2, nw = warp & 3;
    const int r0 = blockIdx.x * 128;
    const uint32_t* gB = d_Bp + (size_t)blockIdx.y * 16 * BCH;

    float acc[4][4][4];
    #pragma unroll
    for (int i = 0; i < 4; i++)
        #pragma unroll
        for (int j = 0; j < 4; j++)
            #pragma unroll
            for (int q = 0; q < 4; q++) acc[i][j][q] = 0.0f;

    const int lrow = tid >> 3;
    const int lkq  = (tid & 7) * 4;

    float4 av4[4];
    #pragma unroll
    for (int q = 0; q < 4; q++)
        av4[q] = *(const float4*)(A + (size_t)(r0 + q * 32 + lrow) * DD + lkq);
    {
        const float4* src = (const float4*)(gB);
        uint32_t dst = smem_u32(Bst);
        #pragma unroll
        for (int i = 0; i < 9; i++)
            CP_ASYNC16(dst + (uint32_t)(tid + i * 256) * 16, src + tid + i * 256);
        CP_COMMIT();
    }

    for (int kc = 0; kc < 16; kc++) {
        const int s = kc & 1;
        uint4 hv[4], lv[4];
        #pragma unroll
        for (int q = 0; q < 4; q++) {
            float4 v = av4[q];
            uint32_t h0 = to_tf32(v.x), h1 = to_tf32(v.y),
                     h2 = to_tf32(v.z), h3 = to_tf32(v.w);
            hv[q] = make_uint4(h0, h1, h2, h3);
            lv[q] = make_uint4(to_tf32(v.x - __uint_as_float(h0)),
                               to_tf32(v.y - __uint_as_float(h1)),
                               to_tf32(v.z - __uint_as_float(h2)),
                               to_tf32(v.w - __uint_as_float(h3)));
        }
        __syncthreads();
        #pragma unroll
        for (int q = 0; q < 4; q++) {
            int m = q * 32 + lrow;
            *(uint4*)&Ah[m * XSTR + lkq] = hv[q];
            *(uint4*)&Al[m * XSTR + lkq] = lv[q];
        }
        if (kc < 15) {
            const float4* src = (const float4*)(gB + (kc + 1) * BCH);
            uint32_t dst = smem_u32(Bst + (s ^ 1) * BCH);
            #pragma unroll
            for (int i = 0; i < 9; i++)
                CP_ASYNC16(dst + (uint32_t)(tid + i * 256) * 16, src + tid + i * 256);
            CP_COMMIT();
            #pragma unroll
            for (int q = 0; q < 4; q++)
                av4[q] = *(const float4*)(A + (size_t)(r0 + q * 32 + lrow) * DD
                                          + (kc + 1) * 32 + lkq);
            CP_WAIT1();
        } else {
            CP_WAIT0();
        }
        __syncthreads();

        const uint32_t* Bh = Bst + s * BCH;
        const uint32_t* Bl = Bh + 4608;
        #pragma unroll
        for (int ka = 0; ka < 4; ka++) {
            const int kb = ka * 8;
            uint32_t bh0[4], bh1[4], bl0[4], bl1[4];
            #pragma unroll
            for (int j = 0; j < 4; j++) {
                int nn = nw * 32 + j * 8 + g;
                bh0[j] = Bh[nn * XSTR + kb + tg];
                bh1[j] = Bh[nn * XSTR + kb + tg + 4];
                bl0[j] = Bl[nn * XSTR + kb + tg];
                bl1[j] = Bl[nn * XSTR + kb + tg + 4];
            }
            #pragma unroll
            for (int i = 0; i < 4; i++) {
                int mm = mw * 64 + i * 16;
                uint32_t ah[4], al[4];
                ah[0] = Ah[(mm + g) * XSTR + kb + tg];
                ah[1] = Ah[(mm + g + 8) * XSTR + kb + tg];
                ah[2] = Ah[(mm + g) * XSTR + kb + tg + 4];
                ah[3] = Ah[(mm + g + 8) * XSTR + kb + tg + 4];
                al[0] = Al[(mm + g) * XSTR + kb + tg];
                al[1] = Al[(mm + g + 8) * XSTR + kb + tg];
                al[2] = Al[(mm + g) * XSTR + kb + tg + 4];
                al[3] = Al[(mm + g + 8) * XSTR + kb + tg + 4];
                #pragma unroll
                for (int j = 0; j < 4; j++) {
                    mma_tf32(acc[i][j], ah, bl0[j], bl1[j]);
                    mma_tf32(acc[i][j], al, bh0[j], bh1[j]);
                    mma_tf32(acc[i][j], ah, bh0[j], bh1[j]);
                }
            }
        }
    }

    const int n0 = blockIdx.y * 128;
    #pragma unroll
    for (int i = 0; i < 4; i++) {
        int m0 = r0 + mw * 64 + i * 16;
        #pragma unroll
        for (int j = 0; j < 4; j++) {
            int n = n0 + nw * 32 + j * 8 + tg * 2;
            *(float2*)(out + (size_t)(m0 + g) * NCOL + n) =
                make_float2(acc[i][j][0], acc[i][j][1]);
            *(float2*)(out + (size_t)(m0 + g + 8) * NCOL + n) =
                make_float2(acc[i][j][2], acc[i][j][3]);
        }
    }
}

// ---------------- fused 4-iteration refine: one block owns one frame ----------------
// smem floats: G2s 8*2048 | X0s 2048 | CSs 2048 | Ss 2048 | cens 8*512 | xe 512 | xs 512
#define ISM_FLOATS (8*NCOL + 3*NCOL + CB*DD + DD + DD)
__global__ void __launch_bounds__(256)
iter4_k(const float* __restrict__ x, const float* __restrict__ centers,
        const float* __restrict__ fes, const int* __restrict__ init_idx,
        uint4 fk0s, uint4 fk1s) {
    extern __shared__ float sm[];
    float* G2s  = sm;                         // 8 x 2048
    float* X0s  = sm + 8 * NCOL;
    float* CSs  = sm + 9 * NCOL;
    float* Ss   = sm + 10 * NCOL;
    float* cens = sm + 11 * NCOL;             // 8 x 512
    float* xe   = sm + 11 * NCOL + CB * DD;
    float* xs   = xe + DD;
    __shared__ int ids[CB];

    const int tid = threadIdx.x;
    const int w = tid >> 5, l = tid & 31;
    const int b = blockIdx.x;

    if (tid < CB) ids[tid] = init_idx[b * CB + tid];
    __syncthreads();

    const float scale = expf(fes[0]);

    for (int it = 0; it < 4; it++) {
        const unsigned fk0 = (it == 0) ? fk0s.x : (it == 1) ? fk0s.y
                           : (it == 2) ? fk0s.z : fk0s.w;
        const unsigned fk1 = (it == 0) ? fk1s.x : (it == 1) ? fk1s.y
                           : (it == 2) ? fk1s.z : fk1s.w;
        const int last = (it == 3);

        // gather (ids-dependent): 8 G2 rows + 8 center rows; iter 0 also X0/censq/x
        #pragma unroll
        for (int c = 0; c < CB; c++) {
            const float4* src = (const float4*)(d_G2 + (size_t)(c * KK + ids[c]) * NCOL);
            uint32_t dst = smem_u32(G2s + c * NCOL);
            CP_ASYNC16(dst + tid * 16, src + tid);
            CP_ASYNC16(dst + (tid + 256) * 16, src + tid + 256);
        }
        #pragma unroll
        for (int q = 0; q < 4; q++) {
            int t = tid + q * 256;            // 0..1023
            int c = t >> 7, f = t & 127;
            const float4* src = (const float4*)(centers + ((size_t)c * KK + ids[c]) * DD) + f;
            CP_ASYNC16(smem_u32(cens + c * DD + f * 4), src);
        }
        if (it == 0) {
            const float4* sx = (const float4*)(d_X0 + (size_t)b * NCOL);
            uint32_t dx = smem_u32(X0s);
            CP_ASYNC16(dx + tid * 16, sx + tid);
            CP_ASYNC16(dx + (tid + 256) * 16, sx + tid + 256);
            const float4* sc = (const float4*)(d_censq);
            uint32_t dc = smem_u32(CSs);
            CP_ASYNC16(dc + tid * 16, sc + tid);
            CP_ASYNC16(dc + (tid + 256) * 16, sc + tid + 256);
            if (tid < 128)
                CP_ASYNC16(smem_u32(xs + tid * 4),
                           (const float4*)(x + (size_t)b * DD) + tid);
        }
        CP_COMMIT();
        CP_WAIT0();
        __syncthreads();

        // xe[d] = (sum_c cens) - x[d]   (same arithmetic/order as asq_k)
        #pragma unroll
        for (int q = 0; q < 2; q++) {
            int d = tid + q * 256;
            float s = 0.0f;
            #pragma unroll
            for (int c = 0; c < CB; c++) s += cens[c * DD + d];
            xe[d] = s - xs[d];
        }
        __syncthreads();

        // a_sq: warp-per-codebook (full-warp value after shuffle; same bits as before)
        float asq = 0.0f;
        #pragma unroll
        for (int it2 = 0; it2 < 16; it2++) {
            int d = l + it2 * 32;
            float a = xe[d] - cens[w * DD + d];
            asq = fmaf(a, a, asq);
        }
        #pragma unroll
        for (int off = 16; off; off >>= 1)
            asq += __shfl_xor_sync(0xffffffffu, asq, off);

        // S[col] = sum_c G2row[c][col], fixed order
        #pragma unroll
        for (int q = 0; q < 8; q++) {
            int col = tid + q * 256;
            float s = 0.0f;
            #pragma unroll
            for (int c = 0; c < CB; c++) s += G2s[c * NCOL + col];
            Ss[col] = s;
        }
        __syncthreads();

        // logits + gumbel + argmax (+stats on last iter) — verbatim ref_k math
        const int c = w;
        const unsigned ebase = ((unsigned)(b * CB + c)) << 8;

        float vs[8];
        float bestS = -INFINITY; int bestK = 0;
        #pragma unroll
        for (int j = 0; j < 8; j++) {
            int k = l + 32 * j;
            int col = c * KK + k;
            float cross = (Ss[col] - X0s[col]) - G2s[c * NCOL + col];
            float v = -((asq + 2.0f * cross) + CSs[col]);   // reference grouping
            vs[j] = v;
            float g = gumbel_elem(fk0, fk1, ebase + (unsigned)k);
            float s = scale * v + g;
            if (s > bestS || (s == bestS && k < bestK)) { bestS = s; bestK = k; }
        }
        #pragma unroll
        for (int off = 16; off; off >>= 1) {
            float oS = __shfl_xor_sync(0xffffffffu, bestS, off);
            int   oK = __shfl_xor_sync(0xffffffffu, bestK, off);
            if (oS > bestS || (oS == bestS && oK < bestK)) { bestS = oS; bestK = oK; }
        }
        if (l == 0) {
            if (last) d_idx[0][b * CB + c] = bestK;
            else      ids[c] = bestK;
        }

        if (last) {
            float m = -INFINITY;
            #pragma unroll
            for (int j = 0; j < 8; j++) m = fmaxf(m, scale * vs[j]);
            #pragma unroll
            for (int off = 16; off; off >>= 1)
                m = fmaxf(m, __shfl_xor_sync(0xffffffffu, m, off));
            float se = 0.0f;
            #pragma unroll
            for (int j = 0; j < 8; j++) se += expf(scale * vs[j] - m);
            #pragma unroll
            for (int off = 16; off; off >>= 1)
                se += __shfl_xor_sync(0xffffffffu, se, off);
            float lse = m + logf(se);
            float H = 0.0f, ES = 0.0f;
            #pragma unroll
            for (int j = 0; j < 8; j++) {
                int k = l + 32 * j;
                float lp = scale * vs[j] - lse;
                float p = expf(lp);
                H  = fmaf(-p, lp, H);
                ES = fmaf(p, -vs[j], ES);
                d_Pb[(size_t)b * NCOL + c * KK + k] = p;
            }
            #pragma unroll
            for (int off = 16; off; off >>= 1) {
                H  += __shfl_xor_sync(0xffffffffu, H, off);
                ES += __shfl_xor_sync(0xffffffffu, ES, off);
            }
            if (l == 0) { d_Hb[b * CB + c] = H; d_ESb[b * CB + c] = ES; }
        }
        __syncthreads();   // ids visible; all smem reads done before next gather
    }
}

// ---------------- last-iter column sums of probs (deterministic) ----------------
__global__ void colsum_k() {
    const int col = blockIdx.y * 256 + threadIdx.x;
    const int bx = blockIdx.x;             // 32 b-chunks of 512
    float s = 0.0f;
    for (int b = bx * 512; b < (bx + 1) * 512; b++)
        s += d_Pb[(size_t)b * NCOL + col];
    d_Pc[bx][col] = s;
}

// ---------------- outputs ----------------
__global__ void outidx_k(float* out, int out_size) {
    int t = blockIdx.x * blockDim.x + threadIdx.x;
    if (t < NIDX && t < out_size) out[t] = (float)d_idx[0][t];
}

__global__ void scal_k(float* out, int out_size) {
    const int t = threadIdx.x;
    __shared__ float sh[256];

    float v = 0.0f;
    for (int i = t; i < NXB; i += 256) v += d_xsqp[i];
    sh[t] = v; __syncthreads();
    for (int s = 128; s; s >>= 1) { if (t < s) sh[t] += sh[t + s]; __syncthreads(); }
    float xsq = sh[0]; __syncthreads();

    v = 0.0f;
    for (int i = t; i < NIDX; i += 256) v += d_Hb[i];
    sh[t] = v; __syncthreads();
    for (int s = 128; s; s >>= 1) { if (t < s) sh[t] += sh[t + s]; __syncthreads(); }
    float Hs = sh[0]; __syncthreads();

    v = 0.0f;
    for (int i = t; i < NIDX; i += 256) v += d_ESb[i];
    sh[t] = v; __syncthreads();
    for (int s = 128; s; s >>= 1) { if (t < s) sh[t] += sh[t + s]; __syncthreads(); }
    float ESs = sh[0]; __syncthreads();

    v = 0.0f;
    for (int col = t; col < NCOL; col += 256) {
        float s = 0.0f;
        #pragma unroll
        for (int bx = 0; bx < 32; bx++) s += d_Pc[bx][col];
        float avg = s / (float)BDIM;
        v += -avg * logf(avg + 1e-20f);
    }
    sh[t] = v; __syncthreads();
    for (int s = 128; s; s >>= 1) { if (t < s) sh[t] += sh[t + s]; __syncthreads(); }
    float cent = sh[0];

    if (t == 0 && out_size >= NIDX + 3) {
        out[NIDX + 0] = logf((float)KK) - cent / (float)CB;  // entropy_loss
        out[NIDX + 1] = Hs / (float)NIDX;                    // frame_entropy
        out[NIDX + 2] = (ESs / (float)CB) / (xsq + 1e-20f);  // reconstruction_loss
    }
}

// ---------------- launch ----------------
extern "C" void kernel_launch(void* const* d_in, const int* in_sizes, int n_in,
                              void* d_out, int out_size) {
    const float* x       = (const float*)d_in[0];
    const float* centers = (const float*)d_in[1];
    const float* fes     = (const float*)d_in[2];
    const int*   init_i  = (const int*)d_in[3];
    float* out = (float*)d_out;
    (void)in_sizes; (void)n_in;

    static int smem_set = 0;
    if (!smem_set) {
        cudaFuncSetAttribute(iter4_k, cudaFuncAttributeMaxDynamicSharedMemorySize,
                             ISM_FLOATS * 4);
        cudaFuncSetAttribute(x0mma_k, cudaFuncAttributeMaxDynamicSharedMemorySize,
                             (2 * 4608 + 2 * BCH) * 4);
        smem_set = 1;
    }

    censq_k<<<NCOL, 128>>>(centers);
    xsq_k<<<NXB, 256>>>(x);
    bprep_k<<<(NCOL * DD) / 256, 256>>>(centers);

    // one-time GEMMs: G2 = CF @ CF^T (fp32 scalar), X0 = x @ CF^T (3xTF32 mma)
    {
        float* G2p; cudaGetSymbolAddress((void**)&G2p, d_G2);
        float* X0p; cudaGetSymbolAddress((void**)&X0p, d_X0);
        dim3 gg(NCOL / 64, CB);
        gemm_k<<<gg, 256>>>(centers, centers, G2p);
        dim3 gx(BDIM / 128, NCOL / 128);
        x0mma_k<<<gx, 256, (2 * 4608 + 2 * BCH) * 4>>>(x, X0p);
    }

    // fused 4-iteration refinement (one block per frame)
    {
        unsigned f0[4], f1[4];
        for (int i = 0; i < 4; i++) {
            unsigned a = 0u, b2 = (unsigned)i;
            tf2x32(0u, 1234u, a, b2);   // fold_in(key(1234), i)
            f0[i] = a; f1[i] = b2;
        }
        uint4 fk0s = make_uint4(f0[0], f0[1], f0[2], f0[3]);
        uint4 fk1s = make_uint4(f1[0], f1[1], f1[2], f1[3]);
        iter4_k<<<BDIM, 256, ISM_FLOATS * 4>>>(x, centers, fes, init_i, fk0s, fk1s);
    }

    {
        dim3 gc(32, CB);
        colsum_k<<<gc, 256>>>();
    }
    outidx_k<<<(NIDX + 255) / 256, 256>>>(out, out_size);
    scal_k<<<1, 256>>>(out, out_size);
}

// round 14
// speedup vs baseline: 1.6189x; 1.1260x over previous
#include <cuda_runtime.h>
#include <math.h>
#include <stdint.h>
#include <stddef.h>

#define BDIM 16384
#define CB   8
#define KK   256
#define DD   512
#define NCOL (CB*KK)              /* 2048 */
#define NIDX (BDIM*CB)            /* 131072 */
#define NXB  1024
#define XSTR 36                   /* smem row stride for mma tiles */
#define BCH  9216                 /* words per B chunk: Bh(4608)+Bl(4608) */

// ---------------- static device scratch (no allocations allowed) ----------------
static __device__ float d_X0[(size_t)BDIM*NCOL];   // x @ centers^T       (134MB)
static __device__ float d_G2[(size_t)NCOL*NCOL];   // centers @ centers^T (16MB)
static __device__ float d_Pb[(size_t)BDIM*NCOL];   // per-frame probs, last iter (134MB)
static __device__ __align__(16) uint32_t d_Bp[16*16*BCH]; // prepacked TF32 B tiles (9.4MB)
static __device__ float d_censq[NCOL];
static __device__ int   d_idx[2][NIDX];
static __device__ float d_Hb[NIDX];
static __device__ float d_ESb[NIDX];
static __device__ float d_Pc[32][NCOL];
static __device__ float d_xsqp[NXB];

// ---------------- Threefry-2x32-20 (exact JAX semantics) ----------------
__host__ __device__ __forceinline__ unsigned rotl32(unsigned x, int r) {
    return (x << r) | (x >> (32 - r));
}
__host__ __device__ __forceinline__ void tf2x32(unsigned k0, unsigned k1,
                                                unsigned& x0, unsigned& x1) {
    unsigned k2 = k0 ^ k1 ^ 0x1BD11BDAu;
    x0 += k0; x1 += k1;
#define TFR(r) { x0 += x1; x1 = rotl32(x1, (r)); x1 ^= x0; }
    TFR(13) TFR(15) TFR(26) TFR(6)   x0 += k1; x1 += k2 + 1u;
    TFR(17) TFR(29) TFR(16) TFR(24)  x0 += k2; x1 += k0 + 2u;
    TFR(13) TFR(15) TFR(26) TFR(6)   x0 += k0; x1 += k1 + 3u;
    TFR(17) TFR(29) TFR(16) TFR(24)  x0 += k1; x1 += k2 + 4u;
    TFR(13) TFR(15) TFR(26) TFR(6)   x0 += k2; x1 += k0 + 5u;
#undef TFR
}

__device__ __forceinline__ float gumbel_from_bits(unsigned r) {
    float f = __uint_as_float((r >> 9) | 0x3f800000u) - 1.0f;
    float u = (f == 0.0f) ? 1.17549435e-38f : f;
    return -logf(-logf(u));
}

// jax_threefry_partitionable random_bits: elem e -> threefry(key,(0,e)), o0^o1
__device__ __forceinline__ float gumbel_elem(unsigned k0, unsigned k1, unsigned e) {
    unsigned x0 = 0u, x1 = e;
    tf2x32(k0, k1, x0, x1);
    return gumbel_from_bits(x0 ^ x1);
}

// ---------------- cp.async + mma helpers ----------------
__device__ __forceinline__ uint32_t smem_u32(const void* p) {
    uint32_t a;
    asm("{ .reg .u64 t; cvta.to.shared.u64 t, %1; cvt.u32.u64 %0, t; }" : "=r"(a) : "l"(p));
    return a;
}
#define CP_ASYNC16(d, s) asm volatile("cp.async.cg.shared.global [%0], [%1], 16;" :: "r"(d), "l"(s) : "memory")
#define CP_COMMIT()      asm volatile("cp.async.commit_group;" ::: "memory")
#define CP_WAIT0()       asm volatile("cp.async.wait_group 0;" ::: "memory")
#define CP_WAIT1()       asm volatile("cp.async.wait_group 1;" ::: "memory")

__device__ __forceinline__ uint32_t to_tf32(float v) {
    uint32_t r;
    asm("cvt.rna.tf32.f32 %0, %1;" : "=r"(r) : "f"(v));
    return r;
}
__device__ __forceinline__ void mma_tf32(float* c, const uint32_t* a,
                                         uint32_t b0, uint32_t b1) {
    asm volatile(
        "mma.sync.aligned.m16n8k8.row.col.f32.tf32.tf32.f32 "
        "{%0,%1,%2,%3}, {%4,%5,%6,%7}, {%8,%9}, {%0,%1,%2,%3};"
        : "+f"(c[0]), "+f"(c[1]), "+f"(c[2]), "+f"(c[3])
        : "r"(a[0]), "r"(a[1]), "r"(a[2]), "r"(a[3]), "r"(b0), "r"(b1));
}

// ---------------- small kernels ----------------
__global__ void censq_k(const float* __restrict__ centers) {
    int row = blockIdx.x;                  // 0..2047
    const float* cc = centers + (size_t)row * DD;
    float p = 0.0f;
    for (int d = threadIdx.x; d < DD; d += 128) p = fmaf(cc[d], cc[d], p);
    #pragma unroll
    for (int off = 16; off; off >>= 1) p += __shfl_xor_sync(0xffffffffu, p, off);
    __shared__ float red[4];
    if ((threadIdx.x & 31) == 0) red[threadIdx.x >> 5] = p;
    __syncthreads();
    if (threadIdx.x == 0) d_censq[row] = ((red[0] + red[1]) + (red[2] + red[3]));
}

__global__ void xsq_k(const float* __restrict__ x) {
    const size_t N = (size_t)BDIM * DD;
    float p = 0.0f;
    for (size_t i = (size_t)blockIdx.x * blockDim.x + threadIdx.x; i < N;
         i += (size_t)gridDim.x * blockDim.x)
        p = fmaf(x[i], x[i], p);
    #pragma unroll
    for (int off = 16; off; off >>= 1) p += __shfl_xor_sync(0xffffffffu, p, off);
    __shared__ float red[8];
    if ((threadIdx.x & 31) == 0) red[threadIdx.x >> 5] = p;
    __syncthreads();
    if (threadIdx.x == 0) {
        float s = 0.0f;
        #pragma unroll
        for (int w = 0; w < 8; w++) s += red[w];
        d_xsqp[blockIdx.x] = s;
    }
}

// ---------------- prepack centers into TF32 hi/lo tiles (smem-layout, padded) ----------------
__global__ void bprep_k(const float* __restrict__ centers) {
    unsigned t = blockIdx.x * blockDim.x + threadIdx.x;   // < 2048*512
    unsigned n = t >> 9, d = t & 511;
    float v = centers[(size_t)n * DD + d];
    uint32_t hi = to_tf32(v);
    uint32_t lo = to_tf32(v - __uint_as_float(hi));
    unsigned nblk = n >> 7, row = n & 127, kc = d >> 5, col = d & 31;
    unsigned base = (nblk * 16 + kc) * BCH;
    d_Bp[base + row * XSTR + col] = hi;
    d_Bp[base + 4608 + row * XSTR + col] = lo;
}

// ---------------- scalar SGEMM (round-7, proven; used for G2 only) ----------------
__global__ __launch_bounds__(256, 2)
void gemm_k(const float* __restrict__ A, const float* __restrict__ centers,
            float* __restrict__ out) {
    __shared__ float As[16][68];
    __shared__ float Bs[16][256];
    const int tid = threadIdx.x;
    const int w = tid >> 5, l = tid & 31;
    const int cy = blockIdx.y;
    const int r0 = blockIdx.x * 64;

    const int lr = tid >> 2, lq = tid & 3;
    const float* aP = A + (size_t)(r0 + lr) * DD + lq * 4;
    const int bk = tid >> 1, bd = (tid & 1) * 8;
    const float* b0P = centers + ((size_t)cy * KK + bk) * DD + bd;
    const float* b1P = centers + ((size_t)cy * KK + 128 + bk) * DD + bd;

    float acc[8][8];
    #pragma unroll
    for (int i = 0; i < 8; i++)
        #pragma unroll
        for (int j = 0; j < 8; j++) acc[i][j] = 0.0f;

    float4 a4 = *(const float4*)(aP);
    float4 q0 = *(const float4*)(b0P);
    float4 q1 = *(const float4*)(b0P + 4);
    float4 q2 = *(const float4*)(b1P);
    float4 q3 = *(const float4*)(b1P + 4);

    for (int kb = 0; kb < 32; kb++) {
        __syncthreads();
        As[lq*4+0][lr] = a4.x; As[lq*4+1][lr] = a4.y;
        As[lq*4+2][lr] = a4.z; As[lq*4+3][lr] = a4.w;
        Bs[bd+0][bk] = q0.x; Bs[bd+1][bk] = q0.y;
        Bs[bd+2][bk] = q0.z; Bs[bd+3][bk] = q0.w;
        Bs[bd+4][bk] = q1.x; Bs[bd+5][bk] = q1.y;
        Bs[bd+6][bk] = q1.z; Bs[bd+7][bk] = q1.w;
        Bs[bd+0][128+bk] = q2.x; Bs[bd+1][128+bk] = q2.y;
        Bs[bd+2][128+bk] = q2.z; Bs[bd+3][128+bk] = q2.w;
        Bs[bd+4][128+bk] = q3.x; Bs[bd+5][128+bk] = q3.y;
        Bs[bd+6][128+bk] = q3.z; Bs[bd+7][128+bk] = q3.w;
        __syncthreads();
        if (kb < 31) {
            const int d0 = (kb + 1) * 16;
            a4 = *(const float4*)(aP + d0);
            q0 = *(const float4*)(b0P + d0);
            q1 = *(const float4*)(b0P + d0 + 4);
            q2 = *(const float4*)(b1P + d0);
            q3 = *(const float4*)(b1P + d0 + 4);
        }
        #pragma unroll
        for (int d = 0; d < 16; d++) {
            float4 a0 = *(const float4*)&As[d][w*8];
            float4 a1 = *(const float4*)&As[d][w*8+4];
            float4 bb0 = *(const float4*)&Bs[d][l*8];
            float4 bb1 = *(const float4*)&Bs[d][l*8+4];
            float av[8] = {a0.x,a0.y,a0.z,a0.w,a1.x,a1.y,a1.z,a1.w};
            float bv[8] = {bb0.x,bb0.y,bb0.z,bb0.w,bb1.x,bb1.y,bb1.z,bb1.w};
            #pragma unroll
            for (int i = 0; i < 8; i++)
                #pragma unroll
                for (int j = 0; j < 8; j++)
                    acc[i][j] = fmaf(av[i], bv[j], acc[i][j]);
        }
    }

    #pragma unroll
    for (int i = 0; i < 8; i++) {
        float* o = out + (size_t)(r0 + w*8 + i) * NCOL + cy * KK + l * 8;
        float4 v0 = make_float4(acc[i][0], acc[i][1], acc[i][2], acc[i][3]);
        float4 v1 = make_float4(acc[i][4], acc[i][5], acc[i][6], acc[i][7]);
        *(float4*)o = v0;
        *(float4*)(o + 4) = v1;
    }
}

// ---------------- X0 GEMM on tensor cores: 3xTF32 mma.sync, pipelined (round-12) ----------------
__global__ __launch_bounds__(256, 2)
void x0mma_k(const float* __restrict__ A, float* __restrict__ out) {
    extern __shared__ uint32_t xsm[];
    uint32_t* Ah  = xsm;                      // [128][XSTR]
    uint32_t* Al  = xsm + 4608;
    uint32_t* Bst = xsm + 2 * 4608;           // 2 stages x BCH (Bh | Bl)

    const int tid  = threadIdx.x;
    const int warp = tid >> 5, lane = tid & 31;
    const int g = lane >> 2, tg = lane & 3;
    const int mw = warp >> 2, nw = warp & 3;
    const int r0 = blockIdx.x * 128;
    const uint32_t* gB = d_Bp + (size_t)blockIdx.y * 16 * BCH;

    float acc[4][4][4];
    #pragma unroll
    for (int i = 0; i < 4; i++)
        #pragma unroll
        for (int j = 0; j < 4; j++)
            #pragma unroll
            for (int q = 0; q < 4; q++) acc[i][j][q] = 0.0f;

    const int lrow = tid >> 3;
    const int lkq  = (tid & 7) * 4;

    float4 av4[4];
    #pragma unroll
    for (int q = 0; q < 4; q++)
        av4[q] = *(const float4*)(A + (size_t)(r0 + q * 32 + lrow) * DD + lkq);
    {
        const float4* src = (const float4*)(gB);
        uint32_t dst = smem_u32(Bst);
        #pragma unroll
        for (int i = 0; i < 9; i++)
            CP_ASYNC16(dst + (uint32_t)(tid + i * 256) * 16, src + tid + i * 256);
        CP_COMMIT();
    }

    for (int kc = 0; kc < 16; kc++) {
        const int s = kc & 1;
        uint4 hv[4], lv[4];
        #pragma unroll
        for (int q = 0; q < 4; q++) {
            float4 v = av4[q];
            uint32_t h0 = to_tf32(v.x), h1 = to_tf32(v.y),
                     h2 = to_tf32(v.z), h3 = to_tf32(v.w);
            hv[q] = make_uint4(h0, h1, h2, h3);
            lv[q] = make_uint4(to_tf32(v.x - __uint_as_float(h0)),
                               to_tf32(v.y - __uint_as_float(h1)),
                               to_tf32(v.z - __uint_as_float(h2)),
                               to_tf32(v.w - __uint_as_float(h3)));
        }
        __syncthreads();
        #pragma unroll
        for (int q = 0; q < 4; q++) {
            int m = q * 32 + lrow;
            *(uint4*)&Ah[m * XSTR + lkq] = hv[q];
            *(uint4*)&Al[m * XSTR + lkq] = lv[q];
        }
        if (kc < 15) {
            const float4* src = (const float4*)(gB + (kc + 1) * BCH);
            uint32_t dst = smem_u32(Bst + (s ^ 1) * BCH);
            #pragma unroll
            for (int i = 0; i < 9; i++)
                CP_ASYNC16(dst + (uint32_t)(tid + i * 256) * 16, src + tid + i * 256);
            CP_COMMIT();
            #pragma unroll
            for (int q = 0; q < 4; q++)
                av4[q] = *(const float4*)(A + (size_t)(r0 + q * 32 + lrow) * DD
                                          + (kc + 1) * 32 + lkq);
            CP_WAIT1();
        } else {
            CP_WAIT0();
        }
        __syncthreads();

        const uint32_t* Bh = Bst + s * BCH;
        const uint32_t* Bl = Bh + 4608;
        #pragma unroll
        for (int ka = 0; ka < 4; ka++) {
            const int kb = ka * 8;
            uint32_t bh0[4], bh1[4], bl0[4], bl1[4];
            #pragma unroll
            for (int j = 0; j < 4; j++) {
                int nn = nw * 32 + j * 8 + g;
                bh0[j] = Bh[nn * XSTR + kb + tg];
                bh1[j] = Bh[nn * XSTR + kb + tg + 4];
                bl0[j] = Bl[nn * XSTR + kb + tg];
                bl1[j] = Bl[nn * XSTR + kb + tg + 4];
            }
            #pragma unroll
            for (int i = 0; i < 4; i++) {
                int mm = mw * 64 + i * 16;
                uint32_t ah[4], al[4];
                ah[0] = Ah[(mm + g) * XSTR + kb + tg];
                ah[1] = Ah[(mm + g + 8) * XSTR + kb + tg];
                ah[2] = Ah[(mm + g) * XSTR + kb + tg + 4];
                ah[3] = Ah[(mm + g + 8) * XSTR + kb + tg + 4];
                al[0] = Al[(mm + g) * XSTR + kb + tg];
                al[1] = Al[(mm + g + 8) * XSTR + kb + tg];
                al[2] = Al[(mm + g) * XSTR + kb + tg + 4];
                al[3] = Al[(mm + g + 8) * XSTR + kb + tg + 4];
                #pragma unroll
                for (int j = 0; j < 4; j++) {
                    mma_tf32(acc[i][j], ah, bl0[j], bl1[j]);
                    mma_tf32(acc[i][j], al, bh0[j], bh1[j]);
                    mma_tf32(acc[i][j], ah, bh0[j], bh1[j]);
                }
            }
        }
    }

    const int n0 = blockIdx.y * 128;
    #pragma unroll
    for (int i = 0; i < 4; i++) {
        int m0 = r0 + mw * 64 + i * 16;
        #pragma unroll
        for (int j = 0; j < 4; j++) {
            int n = n0 + nw * 32 + j * 8 + tg * 2;
            *(float2*)(out + (size_t)(m0 + g) * NCOL + n) =
                make_float2(acc[i][j][0], acc[i][j][1]);
            *(float2*)(out + (size_t)(m0 + g + 8) * NCOL + n) =
                make_float2(acc[i][j][2], acc[i][j][3]);
        }
    }
}

// ---------------- fused 4-iteration refine: one block owns one frame ----------------
// smem floats: Ss 2048 | diag 2048 | X0s 2048 | CSs 2048 | cens 8*512 | xe 512 | xs 512
// (G2 rows are no longer staged: Ss is accumulated from direct coalesced LDGs in the
//  SAME fixed c=0..7 order, stashing the diagonal-block value -> bit-identical.)
#define ISM_FLOATS (4*NCOL + CB*DD + DD + DD)
__global__ void __launch_bounds__(256)
iter4_k(const float* __restrict__ x, const float* __restrict__ centers,
        const float* __restrict__ fes, const int* __restrict__ init_idx,
        uint4 fk0s, uint4 fk1s) {
    extern __shared__ float sm[];
    float* Ss   = sm;                         // 2048
    float* diag = sm + NCOL;                  // 2048
    float* X0s  = sm + 2 * NCOL;
    float* CSs  = sm + 3 * NCOL;
    float* cens = sm + 4 * NCOL;              // 8 x 512
    float* xe   = sm + 4 * NCOL + CB * DD;
    float* xs   = xe + DD;
    __shared__ int ids[CB];

    const int tid = threadIdx.x;
    const int w = tid >> 5, l = tid & 31;
    const int b = blockIdx.x;

    if (tid < CB) ids[tid] = init_idx[b * CB + tid];
    __syncthreads();

    const float scale = expf(fes[0]);

    for (int it = 0; it < 4; it++) {
        const unsigned fk0 = (it == 0) ? fk0s.x : (it == 1) ? fk0s.y
                           : (it == 2) ? fk0s.z : fk0s.w;
        const unsigned fk1 = (it == 0) ? fk1s.x : (it == 1) ? fk1s.y
                           : (it == 2) ? fk1s.z : fk1s.w;
        const int last = (it == 3);

        // gather (ids-dependent): 8 center rows; iter 0 also X0/censq/x
        #pragma unroll
        for (int q = 0; q < 4; q++) {
            int t = tid + q * 256;            // 0..1023
            int c = t >> 7, f = t & 127;
            const float4* src = (const float4*)(centers + ((size_t)c * KK + ids[c]) * DD) + f;
            CP_ASYNC16(smem_u32(cens + c * DD + f * 4), src);
        }
        if (it == 0) {
            const float4* sx = (const float4*)(d_X0 + (size_t)b * NCOL);
            uint32_t dx = smem_u32(X0s);
            CP_ASYNC16(dx + tid * 16, sx + tid);
            CP_ASYNC16(dx + (tid + 256) * 16, sx + tid + 256);
            const float4* sc = (const float4*)(d_censq);
            uint32_t dc = smem_u32(CSs);
            CP_ASYNC16(dc + tid * 16, sc + tid);
            CP_ASYNC16(dc + (tid + 256) * 16, sc + tid + 256);
            if (tid < 128)
                CP_ASYNC16(smem_u32(xs + tid * 4),
                           (const float4*)(x + (size_t)b * DD) + tid);
        }
        CP_COMMIT();

        // S[col] = sum_c G2[row_c][col] in fixed c order (direct LDG, coalesced);
        // stash the diagonal-block value (c == col>>8) -> bit-identical to staged version.
        int rowbase[CB];
        #pragma unroll
        for (int c = 0; c < CB; c++) rowbase[c] = c * KK + ids[c];
        #pragma unroll
        for (int q = 0; q < 8; q++) {
            int col = tid + q * 256;
            float s = 0.0f;
            float dg = 0.0f;
            #pragma unroll
            for (int c = 0; c < CB; c++) {
                float v = d_G2[(size_t)rowbase[c] * NCOL + col];
                if ((col >> 8) == c) dg = v;
                s += v;
            }
            Ss[col] = s;
            diag[col] = dg;
        }
        CP_WAIT0();
        __syncthreads();

        // xe[d] = (sum_c cens) - x[d]   (same arithmetic/order as before)
        #pragma unroll
        for (int q = 0; q < 2; q++) {
            int d = tid + q * 256;
            float s = 0.0f;
            #pragma unroll
            for (int c = 0; c < CB; c++) s += cens[c * DD + d];
            xe[d] = s - xs[d];
        }
        __syncthreads();

        // a_sq: warp-per-codebook (full-warp value after shuffle)
        float asq = 0.0f;
        #pragma unroll
        for (int it2 = 0; it2 < 16; it2++) {
            int d = l + it2 * 32;
            float a = xe[d] - cens[w * DD + d];
            asq = fmaf(a, a, asq);
        }
        #pragma unroll
        for (int off = 16; off; off >>= 1)
            asq += __shfl_xor_sync(0xffffffffu, asq, off);

        // logits + gumbel + argmax (+stats on last iter) — verbatim math
        const int c = w;
        const unsigned ebase = ((unsigned)(b * CB + c)) << 8;

        float vs[8];
        float bestS = -INFINITY; int bestK = 0;
        #pragma unroll
        for (int j = 0; j < 8; j++) {
            int k = l + 32 * j;
            int col = c * KK + k;
            float cross = (Ss[col] - X0s[col]) - diag[col];
            float v = -((asq + 2.0f * cross) + CSs[col]);   // reference grouping
            vs[j] = v;
            float g = gumbel_elem(fk0, fk1, ebase + (unsigned)k);
            float s = scale * v + g;
            if (s > bestS || (s == bestS && k < bestK)) { bestS = s; bestK = k; }
        }
        #pragma unroll
        for (int off = 16; off; off >>= 1) {
            float oS = __shfl_xor_sync(0xffffffffu, bestS, off);
            int   oK = __shfl_xor_sync(0xffffffffu, bestK, off);
            if (oS > bestS || (oS == bestS && oK < bestK)) { bestS = oS; bestK = oK; }
        }
        if (l == 0) {
            if (last) d_idx[0][b * CB + c] = bestK;
            else      ids[c] = bestK;
        }

        if (last) {
            float m = -INFINITY;
            #pragma unroll
            for (int j = 0; j < 8; j++) m = fmaxf(m, scale * vs[j]);
            #pragma unroll
            for (int off = 16; off; off >>= 1)
                m = fmaxf(m, __shfl_xor_sync(0xffffffffu, m, off));
            float se = 0.0f;
            #pragma unroll
            for (int j = 0; j < 8; j++) se += expf(scale * vs[j] - m);
            #pragma unroll
            for (int off = 16; off; off >>= 1)
                se += __shfl_xor_sync(0xffffffffu, se, off);
            float lse = m + logf(se);
            float H = 0.0f, ES = 0.0f;
            #pragma unroll
            for (int j = 0; j < 8; j++) {
                int k = l + 32 * j;
                float lp = scale * vs[j] - lse;
                float p = expf(lp);
                H  = fmaf(-p, lp, H);
                ES = fmaf(p, -vs[j], ES);
                d_Pb[(size_t)b * NCOL + c * KK + k] = p;
            }
            #pragma unroll
            for (int off = 16; off; off >>= 1) {
                H  += __shfl_xor_sync(0xffffffffu, H, off);
                ES += __shfl_xor_sync(0xffffffffu, ES, off);
            }
            if (l == 0) { d_Hb[b * CB + c] = H; d_ESb[b * CB + c] = ES; }
        }
        __syncthreads();   // ids visible; all smem reads done before next gather
    }
}

// ---------------- last-iter column sums of probs (deterministic) ----------------
__global__ void colsum_k() {
    const int col = blockIdx.y * 256 + threadIdx.x;
    const int bx = blockIdx.x;             // 32 b-chunks of 512
    float s = 0.0f;
    for (int b = bx * 512; b < (bx + 1) * 512; b++)
        s += d_Pb[(size_t)b * NCOL + col];
    d_Pc[bx][col] = s;
}

// ---------------- outputs ----------------
__global__ void outidx_k(float* out, int out_size) {
    int t = blockIdx.x * blockDim.x + threadIdx.x;
    if (t < NIDX && t < out_size) out[t] = (float)d_idx[0][t];
}

__global__ void scal_k(float* out, int out_size) {
    const int t = threadIdx.x;
    __shared__ float sh[256];

    float v = 0.0f;
    for (int i = t; i < NXB; i += 256) v += d_xsqp[i];
    sh[t] = v; __syncthreads();
    for (int s = 128; s; s >>= 1) { if (t < s) sh[t] += sh[t + s]; __syncthreads(); }
    float xsq = sh[0]; __syncthreads();

    v = 0.0f;
    for (int i = t; i < NIDX; i += 256) v += d_Hb[i];
    sh[t] = v; __syncthreads();
    for (int s = 128; s; s >>= 1) { if (t < s) sh[t] += sh[t + s]; __syncthreads(); }
    float Hs = sh[0]; __syncthreads();

    v = 0.0f;
    for (int i = t; i < NIDX; i += 256) v += d_ESb[i];
    sh[t] = v; __syncthreads();
    for (int s = 128; s; s >>= 1) { if (t < s) sh[t] += sh[t + s]; __syncthreads(); }
    float ESs = sh[0]; __syncthreads();

    v = 0.0f;
    for (int col = t; col < NCOL; col += 256) {
        float s = 0.0f;
        #pragma unroll
        for (int bx = 0; bx < 32; bx++) s += d_Pc[bx][col];
        float avg = s / (float)BDIM;
        v += -avg * logf(avg + 1e-20f);
    }
    sh[t] = v; __syncthreads();
    for (int s = 128; s; s >>= 1) { if (t < s) sh[t] += sh[t + s]; __syncthreads(); }
    float cent = sh[0];

    if (t == 0 && out_size >= NIDX + 3) {
        out[NIDX + 0] = logf((float)KK) - cent / (float)CB;  // entropy_loss
        out[NIDX + 1] = Hs / (float)NIDX;                    // frame_entropy
        out[NIDX + 2] = (ESs / (float)CB) / (xsq + 1e-20f);  // reconstruction_loss
    }
}

// ---------------- launch ----------------
extern "C" void kernel_launch(void* const* d_in, const int* in_sizes, int n_in,
                              void* d_out, int out_size) {
    const float* x       = (const float*)d_in[0];
    const float* centers = (const float*)d_in[1];
    const float* fes     = (const float*)d_in[2];
    const int*   init_i  = (const int*)d_in[3];
    float* out = (float*)d_out;
    (void)in_sizes; (void)n_in;

    static int smem_set = 0;
    if (!smem_set) {
        cudaFuncSetAttribute(iter4_k, cudaFuncAttributeMaxDynamicSharedMemorySize,
                             ISM_FLOATS * 4);
        cudaFuncSetAttribute(x0mma_k, cudaFuncAttributeMaxDynamicSharedMemorySize,
                             (2 * 4608 + 2 * BCH) * 4);
        smem_set = 1;
    }

    censq_k<<<NCOL, 128>>>(centers);
    xsq_k<<<NXB, 256>>>(x);
    bprep_k<<<(NCOL * DD) / 256, 256>>>(centers);

    // one-time GEMMs: G2 = CF @ CF^T (fp32 scalar), X0 = x @ CF^T (3xTF32 mma)
    {
        float* G2p; cudaGetSymbolAddress((void**)&G2p, d_G2);
        float* X0p; cudaGetSymbolAddress((void**)&X0p, d_X0);
        dim3 gg(NCOL / 64, CB);
        gemm_k<<<gg, 256>>>(centers, centers, G2p);
        dim3 gx(BDIM / 128, NCOL / 128);
        x0mma_k<<<gx, 256, (2 * 4608 + 2 * BCH) * 4>>>(x, X0p);
    }

    // fused 4-iteration refinement (one block per frame)
    {
        unsigned f0[4], f1[4];
        for (int i = 0; i < 4; i++) {
            unsigned a = 0u, b2 = (unsigned)i;
            tf2x32(0u, 1234u, a, b2);   // fold_in(key(1234), i)
            f0[i] = a; f1[i] = b2;
        }
        uint4 fk0s = make_uint4(f0[0], f0[1], f0[2], f0[3]);
        uint4 fk1s = make_uint4(f1[0], f1[1], f1[2], f1[3]);
        iter4_k<<<BDIM, 256, ISM_FLOATS * 4>>>(x, centers, fes, init_i, fk0s, fk1s);
    }

    {
        dim3 gc(32, CB);
        colsum_k<<<gc, 256>>>();
    }
    outidx_k<<<(NIDX + 255) / 256, 256>>>(out, out_size);
    scal_k<<<1, 256>>>(out, out_size);
}